// round 8
// baseline (speedup 1.0000x reference)
#include <cuda_runtime.h>
#include <cuda_bf16.h>
#include <math.h>
#include <stdint.h>

// Problem constants
#define BATCH   2
#define SEQ     2048
#define DMODEL  1024
#define HEADS   16
#define DHEAD   64
#define INNER   (HEADS*DHEAD)      // 1024
#define ROWS    (BATCH*SEQ)        // 4096
#define ATT_SCALE 0.125f
#define MASK_NEG 1000000.0f

// Scratch (allocation-free rule: static __device__ globals)
__device__ float g_q[ROWS*INNER];
__device__ float g_k[ROWS*INNER];
__device__ float g_v[ROWS*INNER];
__device__ float g_o[ROWS*INNER];

// ---------------------------------------------------------------------------
// mma.sync helpers (compute_103-compatible; NO tcgen05 — harness PTX target
// is compute_103 which rejects arch-specific instructions)
// ---------------------------------------------------------------------------
__device__ __forceinline__ void mma_tf32(float* d, const uint32_t* a,
                                         uint32_t b0, uint32_t b1)
{
    asm volatile(
        "mma.sync.aligned.m16n8k8.row.col.f32.tf32.tf32.f32 "
        "{%0,%1,%2,%3}, {%4,%5,%6,%7}, {%8,%9}, {%0,%1,%2,%3};"
        : "+f"(d[0]), "+f"(d[1]), "+f"(d[2]), "+f"(d[3])
        : "r"(a[0]), "r"(a[1]), "r"(a[2]), "r"(a[3]), "r"(b0), "r"(b1));
}

__device__ __forceinline__ void mma_bf16(float* d, const uint32_t* a,
                                         uint32_t b0, uint32_t b1)
{
    asm volatile(
        "mma.sync.aligned.m16n8k16.row.col.f32.bf16.bf16.f32 "
        "{%0,%1,%2,%3}, {%4,%5,%6,%7}, {%8,%9}, {%0,%1,%2,%3};"
        : "+f"(d[0]), "+f"(d[1]), "+f"(d[2]), "+f"(d[3])
        : "r"(a[0]), "r"(a[1]), "r"(a[2]), "r"(a[3]), "r"(b0), "r"(b1));
}

__device__ __forceinline__ uint32_t f2tf32(float x) {
    uint32_t r; asm("cvt.rna.tf32.f32 %0, %1;" : "=r"(r) : "f"(x)); return r;
}

__device__ __forceinline__ void ldmx4t(uint32_t& r0, uint32_t& r1,
                                       uint32_t& r2, uint32_t& r3, uint32_t addr)
{
    asm volatile(
        "ldmatrix.sync.aligned.m8n8.x4.trans.shared.b16 {%0,%1,%2,%3}, [%4];"
        : "=r"(r0), "=r"(r1), "=r"(r2), "=r"(r3) : "r"(addr));
}

// ---------------------------------------------------------------------------
// SGEMM (fp32, proven): q,k must stay fp32-accurate — the reference's fp32
// (logit - 1e6) quantizes masked-row logits to a 0.0625 grid; logit errors
// > ~1e-5 flip grid cells and blow up rel_err.
// ---------------------------------------------------------------------------
__global__ __launch_bounds__(256, 2)
void sgemm128(const float* __restrict__ A, const float* __restrict__ B,
              float* __restrict__ C, int M, int N, int K,
              int ldb, int boff, const float* __restrict__ bias)
{
    __shared__ float As[16][128];
    __shared__ float Bs[16][128];

    const int tid = threadIdx.x;
    const int tx  = tid & 15;
    const int ty  = tid >> 4;
    const int rowBase = blockIdx.y * 128;
    const int colBase = blockIdx.x * 128;

    float acc[8][8];
    #pragma unroll
    for (int i = 0; i < 8; i++)
        #pragma unroll
        for (int j = 0; j < 8; j++) acc[i][j] = 0.f;

    const int arow = tid >> 2;
    const int acol = (tid & 3) * 4;
    const int brow = tid >> 5;
    const int bcol = (tid & 31) * 4;

    for (int k0 = 0; k0 < K; k0 += 16) {
        #pragma unroll
        for (int p = 0; p < 2; p++) {
            int r = arow + p * 64;
            float4 v = *(const float4*)(A + (long)(rowBase + r) * K + k0 + acol);
            As[acol + 0][r] = v.x;
            As[acol + 1][r] = v.y;
            As[acol + 2][r] = v.z;
            As[acol + 3][r] = v.w;
        }
        #pragma unroll
        for (int p = 0; p < 2; p++) {
            int r = brow + p * 8;
            *(float4*)&Bs[r][bcol] =
                *(const float4*)(B + (long)(k0 + r) * ldb + boff + colBase + bcol);
        }
        __syncthreads();

        #pragma unroll
        for (int kk = 0; kk < 16; kk++) {
            float a[8], b[8];
            *(float4*)(a)     = *(const float4*)&As[kk][ty * 8];
            *(float4*)(a + 4) = *(const float4*)&As[kk][ty * 8 + 4];
            *(float4*)(b)     = *(const float4*)&Bs[kk][tx * 8];
            *(float4*)(b + 4) = *(const float4*)&Bs[kk][tx * 8 + 4];
            #pragma unroll
            for (int i = 0; i < 8; i++)
                #pragma unroll
                for (int j = 0; j < 8; j++)
                    acc[i][j] = fmaf(a[i], b[j], acc[i][j]);
        }
        __syncthreads();
    }

    #pragma unroll
    for (int i = 0; i < 8; i++) {
        int r = rowBase + ty * 8 + i;
        #pragma unroll
        for (int j = 0; j < 8; j += 4) {
            int cc = colBase + tx * 8 + j;
            float4 v;
            v.x = acc[i][j + 0];
            v.y = acc[i][j + 1];
            v.z = acc[i][j + 2];
            v.w = acc[i][j + 3];
            if (bias) {
                v.x += bias[cc + 0];
                v.y += bias[cc + 1];
                v.z += bias[cc + 2];
                v.w += bias[cc + 3];
            }
            *(float4*)(C + (long)r * N + cc) = v;
        }
    }
}

// ---------------------------------------------------------------------------
// Flash attention v2 (mma.sync), smem-traffic optimized:
//  - Kt: fp32 [64 d][stride 72] (stride 72 => bank = 8*colc + row_a,
//    conflict-free consumer); key index XOR'd with (d>>2) so the producer's
//    transposed scalar stores are ~2-way instead of 16-way conflicted.
//    tf32 hi/lo split happens in REGISTERS at consume time (halves K smem
//    bytes and producer stores vs storing hi/lo).
//  - V: natural [key][d] bf16 hi/lo, stride 72 (rows 144B => ldmatrix row
//    addresses land on distinct bank groups). Producer stores are vectorized
//    STS.64, consumer uses ldmatrix.m8n8.x4.trans (B fragments direct).
//  QK: tf32 3-term (qh*kh + ql*kh + qh*kl); PV: bf16 3-term.
//  Mask: reproduce reference fp32 rounding s = fl(fl(dot*SCALE) - pen).
// ---------------------------------------------------------------------------
#define KT_BYTES   (64*72*4)            // 18432
#define VT_BYTES   (64*72*2)            // 9216
#define FLASH_SMEM (KT_BYTES + 2*VT_BYTES)  // 36864

__global__ __launch_bounds__(128, 2)
void flash_mma(const float* __restrict__ Q, const float* __restrict__ K,
               const float* __restrict__ V, const int* __restrict__ mask,
               float* __restrict__ O)
{
    extern __shared__ char smem[];
    float* Kt = (float*)smem;                                   // [64][72] fp32, XOR keys
    __nv_bfloat16* VHi = (__nv_bfloat16*)(smem + KT_BYTES);     // [64][72] bf16
    __nv_bfloat16* VLo = (__nv_bfloat16*)(smem + KT_BYTES + VT_BYTES);

    const int b  = blockIdx.z;
    const int h  = blockIdx.y;
    const int n0 = blockIdx.x * 64;

    const int tid   = threadIdx.x;
    const int wid   = tid >> 5;
    const int lane  = tid & 31;
    const int r0    = wid * 16;
    const int row_a = lane >> 2;         // 0..7
    const int colc  = lane & 3;          // 0..3

    const long baseQ = (long)b * SEQ * DMODEL + (long)h * DHEAD;

    // ldmatrix per-thread row mapping: lanes 0-15 -> keys 0..15 (d+0),
    // lanes 16-31 -> keys 0..15 (d+8)
    const int lm_k = lane & 15;
    const int lm_d = (lane >> 4) * 8;
    const uint32_t vhi_base = (uint32_t)__cvta_generic_to_shared(VHi);
    const uint32_t vlo_base = (uint32_t)__cvta_generic_to_shared(VLo);

    // ---- Q fragments (tf32 hi/lo), resident in registers ----
    uint32_t qh[32], ql[32];
    #pragma unroll
    for (int s = 0; s < 8; s++) {
        #pragma unroll
        for (int i = 0; i < 4; i++) {
            int rr = n0 + r0 + row_a + ((i & 1) << 3);
            int kk = (s << 3) + colc + ((i >> 1) << 2);
            float qv = Q[baseQ + (long)rr * DMODEL + kk];
            uint32_t hb = f2tf32(qv);
            qh[s*4 + i] = hb;
            ql[s*4 + i] = f2tf32(qv - __uint_as_float(hb));
        }
    }

    const float pen0 = (1.0f - (float)mask[b*SEQ + n0 + r0 + row_a])     * MASK_NEG;
    const float pen1 = (1.0f - (float)mask[b*SEQ + n0 + r0 + row_a + 8]) * MASK_NEG;

    float Oacc[32];
    #pragma unroll
    for (int i = 0; i < 32; i++) Oacc[i] = 0.f;
    float mstat[2] = {-1e30f, -1e30f};
    float lstat[2] = {0.f, 0.f};

    for (int kt = 0; kt < SEQ / 64; kt++) {
        const int m0 = kt * 64;
        __syncthreads();   // previous iteration's smem readers done

        // ---- producer: K transposed fp32 (XOR-swizzled), V natural bf16 hi/lo
        #pragma unroll
        for (int p = 0; p < 8; p++) {
            int idx = tid + p * 128;
            int r = idx >> 4;                // key 0..63
            int c = (idx & 15) << 2;         // d base
            float4 kv = *(const float4*)(K + baseQ + (long)(m0 + r) * DMODEL + c);
            float4 vv = *(const float4*)(V + baseQ + (long)(m0 + r) * DMODEL + c);
            float kf[4] = {kv.x, kv.y, kv.z, kv.w};
            #pragma unroll
            for (int i = 0; i < 4; i++) {
                int d = c + i;
                Kt[d * 72 + (r ^ (d >> 2))] = kf[i];
            }
            float vf[4] = {vv.x, vv.y, vv.z, vv.w};
            __nv_bfloat16 vh[4], vl[4];
            #pragma unroll
            for (int i = 0; i < 4; i++) {
                vh[i] = __float2bfloat16(vf[i]);
                vl[i] = __float2bfloat16(vf[i] - __bfloat162float(vh[i]));
            }
            uint2 ph, pl;
            ph.x = ((uint32_t)__bfloat16_as_ushort(vh[1]) << 16) | __bfloat16_as_ushort(vh[0]);
            ph.y = ((uint32_t)__bfloat16_as_ushort(vh[3]) << 16) | __bfloat16_as_ushort(vh[2]);
            pl.x = ((uint32_t)__bfloat16_as_ushort(vl[1]) << 16) | __bfloat16_as_ushort(vl[0]);
            pl.y = ((uint32_t)__bfloat16_as_ushort(vl[3]) << 16) | __bfloat16_as_ushort(vl[2]);
            *(uint2*)&VHi[r * 72 + c] = ph;
            *(uint2*)&VLo[r * 72 + c] = pl;
        }
        __syncthreads();

        // ---- S = Q K^T (tf32 3-term); K split to hi/lo in registers ----
        float S[32];
        #pragma unroll
        for (int i = 0; i < 32; i++) S[i] = 0.f;

        #pragma unroll
        for (int s = 0; s < 8; s++) {
            const int x0 = 2 * s;
            const int x1 = 2 * s + 1;
            const int rb0 = (s * 8 + colc) * 72;
            const int rb1 = (s * 8 + colc + 4) * 72;
            #pragma unroll
            for (int j = 0; j < 8; j++) {
                int key = j * 8 + row_a;
                float f0 = Kt[rb0 + (key ^ x0)];
                float f1 = Kt[rb1 + (key ^ x1)];
                uint32_t bh0 = f2tf32(f0);
                uint32_t bh1 = f2tf32(f1);
                uint32_t bl0 = f2tf32(f0 - __uint_as_float(bh0));
                uint32_t bl1 = f2tf32(f1 - __uint_as_float(bh1));
                mma_tf32(&S[j*4], &qh[s*4], bh0, bh1);
                mma_tf32(&S[j*4], &ql[s*4], bh0, bh1);
                mma_tf32(&S[j*4], &qh[s*4], bl0, bl1);
            }
        }

        // ---- scale + mask (reference fp32 rounding) + online softmax ----
        #pragma unroll
        for (int t = 0; t < 2; t++) {
            float pent = t ? pen1 : pen0;
            float mloc = -1e30f;
            #pragma unroll
            for (int j = 0; j < 8; j++) {
                float v0 = S[j*4 + 2*t]     * ATT_SCALE - pent;
                float v1 = S[j*4 + 2*t + 1] * ATT_SCALE - pent;
                S[j*4 + 2*t]     = v0;
                S[j*4 + 2*t + 1] = v1;
                mloc = fmaxf(mloc, fmaxf(v0, v1));
            }
            mloc = fmaxf(mloc, __shfl_xor_sync(0xffffffffu, mloc, 1));
            mloc = fmaxf(mloc, __shfl_xor_sync(0xffffffffu, mloc, 2));
            float mnew  = fmaxf(mstat[t], mloc);
            float alpha = __expf(mstat[t] - mnew);
            float lloc = 0.f;
            #pragma unroll
            for (int j = 0; j < 8; j++) {
                float p0 = __expf(S[j*4 + 2*t]     - mnew);
                float p1 = __expf(S[j*4 + 2*t + 1] - mnew);
                S[j*4 + 2*t]     = p0;
                S[j*4 + 2*t + 1] = p1;
                lloc += p0 + p1;
            }
            lloc += __shfl_xor_sync(0xffffffffu, lloc, 1);
            lloc += __shfl_xor_sync(0xffffffffu, lloc, 2);
            lstat[t] = lstat[t] * alpha + lloc;
            mstat[t] = mnew;
            #pragma unroll
            for (int j = 0; j < 8; j++) {
                Oacc[j*4 + 2*t]     *= alpha;
                Oacc[j*4 + 2*t + 1] *= alpha;
            }
        }

        // ---- O += P V (bf16 3-term); V B-frags via ldmatrix.x4.trans ----
        #pragma unroll
        for (int t2 = 0; t2 < 4; t2++) {
            uint32_t ah[4], al[4];
            #pragma unroll
            for (int i = 0; i < 4; i++) {
                int jt  = 2*t2 + (i >> 1);
                int off = (i & 1) * 2;
                float p0 = S[jt*4 + off];
                float p1 = S[jt*4 + off + 1];
                __nv_bfloat16 h0 = __float2bfloat16(p0);
                __nv_bfloat16 h1 = __float2bfloat16(p1);
                ah[i] = ((uint32_t)__bfloat16_as_ushort(h1) << 16) |
                        (uint32_t)__bfloat16_as_ushort(h0);
                __nv_bfloat16 l0 = __float2bfloat16(p0 - __bfloat162float(h0));
                __nv_bfloat16 l1 = __float2bfloat16(p1 - __bfloat162float(h1));
                al[i] = ((uint32_t)__bfloat16_as_ushort(l1) << 16) |
                        (uint32_t)__bfloat16_as_ushort(l0);
            }
            const uint32_t row_off =
                (uint32_t)(((t2 * 16 + lm_k) * 72 + lm_d) * 2);
            #pragma unroll
            for (int j2 = 0; j2 < 4; j2++) {
                uint32_t off = row_off + (uint32_t)(j2 * 16 * 2);
                uint32_t h0, h1, h2, h3, l0, l1, l2, l3;
                ldmx4t(h0, h1, h2, h3, vhi_base + off);
                ldmx4t(l0, l1, l2, l3, vlo_base + off);
                // d-tile 2*j2
                mma_bf16(&Oacc[(2*j2)*4], ah, h0, h1);
                mma_bf16(&Oacc[(2*j2)*4], al, h0, h1);
                mma_bf16(&Oacc[(2*j2)*4], ah, l0, l1);
                // d-tile 2*j2+1
                mma_bf16(&Oacc[(2*j2+1)*4], ah, h2, h3);
                mma_bf16(&Oacc[(2*j2+1)*4], al, h2, h3);
                mma_bf16(&Oacc[(2*j2+1)*4], ah, l2, l3);
            }
        }
    }

    // ---- normalize + store ----
    float inv0 = 1.f / lstat[0];
    float inv1 = 1.f / lstat[1];
    int rowg = n0 + r0 + row_a;
    #pragma unroll
    for (int j = 0; j < 8; j++) {
        float2 v0 = make_float2(Oacc[j*4 + 0] * inv0, Oacc[j*4 + 1] * inv0);
        float2 v1 = make_float2(Oacc[j*4 + 2] * inv1, Oacc[j*4 + 3] * inv1);
        *(float2*)(O + baseQ + (long)rowg       * DMODEL + j*8 + 2*colc) = v0;
        *(float2*)(O + baseQ + (long)(rowg + 8) * DMODEL + j*8 + 2*colc) = v1;
    }
}

// ---------------------------------------------------------------------------
// Launch
// ---------------------------------------------------------------------------
extern "C" void kernel_launch(void* const* d_in, const int* in_sizes, int n_in,
                              void* d_out, int out_size)
{
    const float* x       = (const float*)d_in[0];
    const float* context = (const float*)d_in[1];
    const int*   mask    = (const int*)d_in[2];
    const float* Wq      = (const float*)d_in[3];
    const float* Wkv     = (const float*)d_in[4];
    const float* Wout    = (const float*)d_in[5];
    const float* bout    = (const float*)d_in[6];
    float* out = (float*)d_out;

    float *q, *k, *v, *o;
    cudaGetSymbolAddress((void**)&q, g_q);
    cudaGetSymbolAddress((void**)&k, g_k);
    cudaGetSymbolAddress((void**)&v, g_v);
    cudaGetSymbolAddress((void**)&o, g_o);

    cudaFuncSetAttribute(flash_mma,
                         cudaFuncAttributeMaxDynamicSharedMemorySize, FLASH_SMEM);

    dim3 blk(256);
    dim3 grid_proj(INNER / 128, ROWS / 128);   // (8, 32)

    // q = x @ Wq ; k,v = context @ Wkv (fp32 — precision-critical for q,k)
    sgemm128<<<grid_proj, blk>>>(x, Wq, q, ROWS, INNER, DMODEL, INNER, 0, nullptr);
    sgemm128<<<grid_proj, blk>>>(context, Wkv, k, ROWS, INNER, DMODEL, 2 * INNER, 0, nullptr);
    sgemm128<<<grid_proj, blk>>>(context, Wkv, v, ROWS, INNER, DMODEL, 2 * INNER, INNER, nullptr);

    // attention on tensor cores
    dim3 grid_attn(SEQ / 64, HEADS, BATCH);
    flash_mma<<<grid_attn, 128, FLASH_SMEM>>>(q, k, v, mask, o);

    // out = o @ Wout + bout
    sgemm128<<<grid_proj, blk>>>(o, Wout, out, ROWS, DMODEL, INNER, DMODEL, 0, bout);
}

// round 9
// speedup vs baseline: 1.7299x; 1.7299x over previous
#include <cuda_runtime.h>
#include <cuda_bf16.h>
#include <math.h>
#include <stdint.h>

// Problem constants
#define BATCH   2
#define SEQ     2048
#define DMODEL  1024
#define HEADS   16
#define DHEAD   64
#define INNER   (HEADS*DHEAD)      // 1024
#define ROWS    (BATCH*SEQ)        // 4096
#define ATT_SCALE 0.125f
#define MASK_NEG 1000000.0f

// Scratch (allocation-free rule: static __device__ globals)
__device__ float g_q[ROWS*INNER];
__device__ float g_k[ROWS*INNER];
__device__ float g_v[ROWS*INNER];
__device__ float g_o[ROWS*INNER];

// ---------------------------------------------------------------------------
// mma.sync helpers (compute_103-compatible; NO tcgen05 — harness PTX target
// is compute_103 which rejects arch-specific instructions)
// ---------------------------------------------------------------------------
__device__ __forceinline__ void mma_tf32(float* d, const uint32_t* a,
                                         uint32_t b0, uint32_t b1)
{
    asm volatile(
        "mma.sync.aligned.m16n8k8.row.col.f32.tf32.tf32.f32 "
        "{%0,%1,%2,%3}, {%4,%5,%6,%7}, {%8,%9}, {%0,%1,%2,%3};"
        : "+f"(d[0]), "+f"(d[1]), "+f"(d[2]), "+f"(d[3])
        : "r"(a[0]), "r"(a[1]), "r"(a[2]), "r"(a[3]), "r"(b0), "r"(b1));
}

__device__ __forceinline__ void mma_bf16(float* d, const uint32_t* a,
                                         uint32_t b0, uint32_t b1)
{
    asm volatile(
        "mma.sync.aligned.m16n8k16.row.col.f32.bf16.bf16.f32 "
        "{%0,%1,%2,%3}, {%4,%5,%6,%7}, {%8,%9}, {%0,%1,%2,%3};"
        : "+f"(d[0]), "+f"(d[1]), "+f"(d[2]), "+f"(d[3])
        : "r"(a[0]), "r"(a[1]), "r"(a[2]), "r"(a[3]), "r"(b0), "r"(b1));
}

__device__ __forceinline__ uint32_t f2tf32(float x) {
    uint32_t r; asm("cvt.rna.tf32.f32 %0, %1;" : "=r"(r) : "f"(x)); return r;
}

// pack two floats into bf16x2 (lo_val -> low half, hi_val -> high half).
// cvt.rn.bf16x2.f32 d, a, b : a -> upper, b -> lower. Same RN rounding as
// __float2bfloat16 -> bit-identical to the previous scalar path.
__device__ __forceinline__ uint32_t pack_bf16x2(float lo_val, float hi_val) {
    uint32_t r;
    asm("cvt.rn.bf16x2.f32 %0, %1, %2;" : "=r"(r) : "f"(hi_val), "f"(lo_val));
    return r;
}

__device__ __forceinline__ void ldmx4t(uint32_t& r0, uint32_t& r1,
                                       uint32_t& r2, uint32_t& r3, uint32_t addr)
{
    asm volatile(
        "ldmatrix.sync.aligned.m8n8.x4.trans.shared.b16 {%0,%1,%2,%3}, [%4];"
        : "=r"(r0), "=r"(r1), "=r"(r2), "=r"(r3) : "r"(addr));
}

__device__ __forceinline__ void cp_async16(uint32_t saddr, const void* gptr) {
    asm volatile("cp.async.cg.shared.global [%0], [%1], 16;"
                 :: "r"(saddr), "l"(gptr));
}
__device__ __forceinline__ void cp_async_commit() {
    asm volatile("cp.async.commit_group;");
}
__device__ __forceinline__ void cp_async_wait0() {
    asm volatile("cp.async.wait_group 0;");
}

// ---------------------------------------------------------------------------
// SGEMM (fp32, proven): q,k must stay fp32-accurate — the reference's fp32
// (logit - 1e6) quantizes masked-row logits to a 0.0625 grid; logit errors
// > ~1e-5 flip grid cells and blow up rel_err.
// ---------------------------------------------------------------------------
__global__ __launch_bounds__(256, 2)
void sgemm128(const float* __restrict__ A, const float* __restrict__ B,
              float* __restrict__ C, int M, int N, int K,
              int ldb, int boff, const float* __restrict__ bias)
{
    __shared__ float As[16][128];
    __shared__ float Bs[16][128];

    const int tid = threadIdx.x;
    const int tx  = tid & 15;
    const int ty  = tid >> 4;
    const int rowBase = blockIdx.y * 128;
    const int colBase = blockIdx.x * 128;

    float acc[8][8];
    #pragma unroll
    for (int i = 0; i < 8; i++)
        #pragma unroll
        for (int j = 0; j < 8; j++) acc[i][j] = 0.f;

    const int arow = tid >> 2;
    const int acol = (tid & 3) * 4;
    const int brow = tid >> 5;
    const int bcol = (tid & 31) * 4;

    for (int k0 = 0; k0 < K; k0 += 16) {
        #pragma unroll
        for (int p = 0; p < 2; p++) {
            int r = arow + p * 64;
            float4 v = *(const float4*)(A + (long)(rowBase + r) * K + k0 + acol);
            As[acol + 0][r] = v.x;
            As[acol + 1][r] = v.y;
            As[acol + 2][r] = v.z;
            As[acol + 3][r] = v.w;
        }
        #pragma unroll
        for (int p = 0; p < 2; p++) {
            int r = brow + p * 8;
            *(float4*)&Bs[r][bcol] =
                *(const float4*)(B + (long)(k0 + r) * ldb + boff + colBase + bcol);
        }
        __syncthreads();

        #pragma unroll
        for (int kk = 0; kk < 16; kk++) {
            float a[8], b[8];
            *(float4*)(a)     = *(const float4*)&As[kk][ty * 8];
            *(float4*)(a + 4) = *(const float4*)&As[kk][ty * 8 + 4];
            *(float4*)(b)     = *(const float4*)&Bs[kk][tx * 8];
            *(float4*)(b + 4) = *(const float4*)&Bs[kk][tx * 8 + 4];
            #pragma unroll
            for (int i = 0; i < 8; i++)
                #pragma unroll
                for (int j = 0; j < 8; j++)
                    acc[i][j] = fmaf(a[i], b[j], acc[i][j]);
        }
        __syncthreads();
    }

    #pragma unroll
    for (int i = 0; i < 8; i++) {
        int r = rowBase + ty * 8 + i;
        #pragma unroll
        for (int j = 0; j < 8; j += 4) {
            int cc = colBase + tx * 8 + j;
            float4 v;
            v.x = acc[i][j + 0];
            v.y = acc[i][j + 1];
            v.z = acc[i][j + 2];
            v.w = acc[i][j + 3];
            if (bias) {
                v.x += bias[cc + 0];
                v.y += bias[cc + 1];
                v.z += bias[cc + 2];
                v.w += bias[cc + 3];
            }
            *(float4*)(C + (long)r * N + cc) = v;
        }
    }
}

// ---------------------------------------------------------------------------
// Flash attention v3 (mma.sync), pipelined:
//  - cp.async stages raw K/V fp32 tiles into smem, overlapped with compute
//    of the previous tile (removes exposed GMEM latency, no register cost).
//  - convert phase: K split to tf32 hi/lo IN PRODUCER into the conflict-free
//    XOR layout (consumer inner loop = pure LDS.32 + mma, no cvt); V packed
//    to bf16 hi/lo rows for ldmatrix.x4.trans consumption.
//  QK: tf32 3-term; PV: bf16 3-term. All rounding identical to R7/R8.
//  Mask: reproduce reference fp32 rounding s = fl(fl(dot*SCALE) - pen).
// ---------------------------------------------------------------------------
#define KT_HI   0
#define KT_LO   18432                    // 64*72*4
#define V_HI    36864
#define V_LO    46080                    // + 64*72*2
#define STG_K   55296
#define STG_V   71680                    // + 64*64*4
#define FLASH_SMEM 88064                 // STG_V + 16384

__global__ __launch_bounds__(128, 2)
void flash_mma(const float* __restrict__ Q, const float* __restrict__ K,
               const float* __restrict__ V, const int* __restrict__ mask,
               float* __restrict__ O)
{
    extern __shared__ char smem[];
    float* KtHi = (float*)(smem + KT_HI);                 // [64 d][72], XOR keys
    float* KtLo = (float*)(smem + KT_LO);
    __nv_bfloat16* VHi = (__nv_bfloat16*)(smem + V_HI);   // [64 key][72]
    __nv_bfloat16* VLo = (__nv_bfloat16*)(smem + V_LO);
    float* StgK = (float*)(smem + STG_K);                 // [64][64] raw
    float* StgV = (float*)(smem + STG_V);

    const uint32_t sbase = (uint32_t)__cvta_generic_to_shared(smem);

    const int b  = blockIdx.z;
    const int h  = blockIdx.y;
    const int n0 = blockIdx.x * 64;

    const int tid   = threadIdx.x;
    const int wid   = tid >> 5;
    const int lane  = tid & 31;
    const int r0    = wid * 16;
    const int row_a = lane >> 2;         // 0..7
    const int colc  = lane & 3;          // 0..3

    const long baseQ = (long)b * SEQ * DMODEL + (long)h * DHEAD;

    const int lm_k = lane & 15;
    const int lm_d = (lane >> 4) * 8;
    const uint32_t vhi_base = sbase + V_HI;
    const uint32_t vlo_base = sbase + V_LO;

    // staging chunk coords for this thread (8 chunks per array)
    const int sg_r = tid >> 4;           // +8 per p
    const int sg_c = (tid & 15) << 2;

    // ---- prefetch tile 0 ----
    {
        #pragma unroll
        for (int p = 0; p < 8; p++) {
            int r = sg_r + p * 8;
            uint32_t so = (uint32_t)((r * 64 + sg_c) * 4);
            const float* gk = K + baseQ + (long)r * DMODEL + sg_c;
            const float* gv = V + baseQ + (long)r * DMODEL + sg_c;
            cp_async16(sbase + STG_K + so, gk);
            cp_async16(sbase + STG_V + so, gv);
        }
        cp_async_commit();
    }

    // ---- Q fragments (tf32 hi/lo), resident in registers ----
    uint32_t qh[32], ql[32];
    #pragma unroll
    for (int s = 0; s < 8; s++) {
        #pragma unroll
        for (int i = 0; i < 4; i++) {
            int rr = n0 + r0 + row_a + ((i & 1) << 3);
            int kk = (s << 3) + colc + ((i >> 1) << 2);
            float qv = Q[baseQ + (long)rr * DMODEL + kk];
            uint32_t hb = f2tf32(qv);
            qh[s*4 + i] = hb;
            ql[s*4 + i] = f2tf32(qv - __uint_as_float(hb));
        }
    }

    const float pen0 = (1.0f - (float)mask[b*SEQ + n0 + r0 + row_a])     * MASK_NEG;
    const float pen1 = (1.0f - (float)mask[b*SEQ + n0 + r0 + row_a + 8]) * MASK_NEG;

    float Oacc[32];
    #pragma unroll
    for (int i = 0; i < 32; i++) Oacc[i] = 0.f;
    float mstat[2] = {-1e30f, -1e30f};
    float lstat[2] = {0.f, 0.f};

    cp_async_wait0();
    __syncthreads();

    for (int kt = 0; kt < SEQ / 64; kt++) {
        // ---- convert staging -> operand buffers ----
        #pragma unroll
        for (int p = 0; p < 8; p++) {
            int r = sg_r + p * 8;            // key
            int c = sg_c;                    // d base
            float4 kv = *(const float4*)(StgK + r * 64 + c);
            float4 vv = *(const float4*)(StgV + r * 64 + c);
            float kf[4] = {kv.x, kv.y, kv.z, kv.w};
            #pragma unroll
            for (int i = 0; i < 4; i++) {
                int d = c + i;
                uint32_t hb = f2tf32(kf[i]);
                int idx = d * 72 + (r ^ (d >> 2));
                KtHi[idx] = __uint_as_float(hb);
                KtLo[idx] = __uint_as_float(f2tf32(kf[i] - __uint_as_float(hb)));
            }
            uint2 ph, pl;
            ph.x = pack_bf16x2(vv.x, vv.y);
            ph.y = pack_bf16x2(vv.z, vv.w);
            pl.x = pack_bf16x2(vv.x - __uint_as_float(ph.x << 16),
                               vv.y - __uint_as_float(ph.x & 0xFFFF0000u));
            pl.y = pack_bf16x2(vv.z - __uint_as_float(ph.y << 16),
                               vv.w - __uint_as_float(ph.y & 0xFFFF0000u));
            *(uint2*)&VHi[r * 72 + c] = ph;
            *(uint2*)&VLo[r * 72 + c] = pl;
        }
        __syncthreads();   // operands ready; staging reusable

        // ---- prefetch next tile into staging (overlaps compute) ----
        if (kt + 1 < SEQ / 64) {
            const int m1 = (kt + 1) * 64;
            #pragma unroll
            for (int p = 0; p < 8; p++) {
                int r = sg_r + p * 8;
                uint32_t so = (uint32_t)((r * 64 + sg_c) * 4);
                const float* gk = K + baseQ + (long)(m1 + r) * DMODEL + sg_c;
                const float* gv = V + baseQ + (long)(m1 + r) * DMODEL + sg_c;
                cp_async16(sbase + STG_K + so, gk);
                cp_async16(sbase + STG_V + so, gv);
            }
            cp_async_commit();
        }

        // ---- S = Q K^T (tf32 3-term); K hi/lo pre-split in smem ----
        float S[32];
        #pragma unroll
        for (int i = 0; i < 32; i++) S[i] = 0.f;

        #pragma unroll
        for (int s = 0; s < 8; s++) {
            const int x0 = 2 * s;
            const int x1 = 2 * s + 1;
            const int rb0 = (s * 8 + colc) * 72;
            const int rb1 = (s * 8 + colc + 4) * 72;
            #pragma unroll
            for (int j = 0; j < 8; j++) {
                int key  = j * 8 + row_a;
                int i0   = rb0 + (key ^ x0);
                int i1   = rb1 + (key ^ x1);
                uint32_t bh0 = __float_as_uint(KtHi[i0]);
                uint32_t bh1 = __float_as_uint(KtHi[i1]);
                uint32_t bl0 = __float_as_uint(KtLo[i0]);
                uint32_t bl1 = __float_as_uint(KtLo[i1]);
                mma_tf32(&S[j*4], &qh[s*4], bh0, bh1);
                mma_tf32(&S[j*4], &ql[s*4], bh0, bh1);
                mma_tf32(&S[j*4], &qh[s*4], bl0, bl1);
            }
        }

        // ---- scale + mask (reference fp32 rounding) + online softmax ----
        #pragma unroll
        for (int t = 0; t < 2; t++) {
            float pent = t ? pen1 : pen0;
            float mloc = -1e30f;
            #pragma unroll
            for (int j = 0; j < 8; j++) {
                float v0 = S[j*4 + 2*t]     * ATT_SCALE - pent;
                float v1 = S[j*4 + 2*t + 1] * ATT_SCALE - pent;
                S[j*4 + 2*t]     = v0;
                S[j*4 + 2*t + 1] = v1;
                mloc = fmaxf(mloc, fmaxf(v0, v1));
            }
            mloc = fmaxf(mloc, __shfl_xor_sync(0xffffffffu, mloc, 1));
            mloc = fmaxf(mloc, __shfl_xor_sync(0xffffffffu, mloc, 2));
            float mnew  = fmaxf(mstat[t], mloc);
            float alpha = __expf(mstat[t] - mnew);
            float lloc = 0.f;
            #pragma unroll
            for (int j = 0; j < 8; j++) {
                float p0 = __expf(S[j*4 + 2*t]     - mnew);
                float p1 = __expf(S[j*4 + 2*t + 1] - mnew);
                S[j*4 + 2*t]     = p0;
                S[j*4 + 2*t + 1] = p1;
                lloc += p0 + p1;
            }
            lloc += __shfl_xor_sync(0xffffffffu, lloc, 1);
            lloc += __shfl_xor_sync(0xffffffffu, lloc, 2);
            lstat[t] = lstat[t] * alpha + lloc;
            mstat[t] = mnew;
            #pragma unroll
            for (int j = 0; j < 8; j++) {
                Oacc[j*4 + 2*t]     *= alpha;
                Oacc[j*4 + 2*t + 1] *= alpha;
            }
        }

        // ---- O += P V (bf16 3-term); V B-frags via ldmatrix.x4.trans ----
        #pragma unroll
        for (int t2 = 0; t2 < 4; t2++) {
            uint32_t ah[4], al[4];
            #pragma unroll
            for (int i = 0; i < 4; i++) {
                int jt  = 2*t2 + (i >> 1);
                int off = (i & 1) * 2;
                float p0 = S[jt*4 + off];
                float p1 = S[jt*4 + off + 1];
                uint32_t hh = pack_bf16x2(p0, p1);
                ah[i] = hh;
                al[i] = pack_bf16x2(p0 - __uint_as_float(hh << 16),
                                    p1 - __uint_as_float(hh & 0xFFFF0000u));
            }
            const uint32_t row_off =
                (uint32_t)(((t2 * 16 + lm_k) * 72 + lm_d) * 2);
            #pragma unroll
            for (int j2 = 0; j2 < 4; j2++) {
                uint32_t off = row_off + (uint32_t)(j2 * 16 * 2);
                uint32_t h0, h1, h2, h3, l0, l1, l2, l3;
                ldmx4t(h0, h1, h2, h3, vhi_base + off);
                ldmx4t(l0, l1, l2, l3, vlo_base + off);
                mma_bf16(&Oacc[(2*j2)*4], ah, h0, h1);
                mma_bf16(&Oacc[(2*j2)*4], al, h0, h1);
                mma_bf16(&Oacc[(2*j2)*4], ah, l0, l1);
                mma_bf16(&Oacc[(2*j2+1)*4], ah, h2, h3);
                mma_bf16(&Oacc[(2*j2+1)*4], al, h2, h3);
                mma_bf16(&Oacc[(2*j2+1)*4], ah, l2, l3);
            }
        }

        if (kt + 1 < SEQ / 64) cp_async_wait0();
        __syncthreads();   // compute done reading operands; staging data visible
    }

    // ---- normalize + store ----
    float inv0 = 1.f / lstat[0];
    float inv1 = 1.f / lstat[1];
    int rowg = n0 + r0 + row_a;
    #pragma unroll
    for (int j = 0; j < 8; j++) {
        float2 v0 = make_float2(Oacc[j*4 + 0] * inv0, Oacc[j*4 + 1] * inv0);
        float2 v1 = make_float2(Oacc[j*4 + 2] * inv1, Oacc[j*4 + 3] * inv1);
        *(float2*)(O + baseQ + (long)rowg       * DMODEL + j*8 + 2*colc) = v0;
        *(float2*)(O + baseQ + (long)(rowg + 8) * DMODEL + j*8 + 2*colc) = v1;
    }
}

// ---------------------------------------------------------------------------
// Launch
// ---------------------------------------------------------------------------
extern "C" void kernel_launch(void* const* d_in, const int* in_sizes, int n_in,
                              void* d_out, int out_size)
{
    const float* x       = (const float*)d_in[0];
    const float* context = (const float*)d_in[1];
    const int*   mask    = (const int*)d_in[2];
    const float* Wq      = (const float*)d_in[3];
    const float* Wkv     = (const float*)d_in[4];
    const float* Wout    = (const float*)d_in[5];
    const float* bout    = (const float*)d_in[6];
    float* out = (float*)d_out;

    float *q, *k, *v, *o;
    cudaGetSymbolAddress((void**)&q, g_q);
    cudaGetSymbolAddress((void**)&k, g_k);
    cudaGetSymbolAddress((void**)&v, g_v);
    cudaGetSymbolAddress((void**)&o, g_o);

    cudaFuncSetAttribute(flash_mma,
                         cudaFuncAttributeMaxDynamicSharedMemorySize, FLASH_SMEM);

    dim3 blk(256);
    dim3 grid_proj(INNER / 128, ROWS / 128);   // (8, 32)

    // q = x @ Wq ; k,v = context @ Wkv (fp32 — precision-critical for q,k)
    sgemm128<<<grid_proj, blk>>>(x, Wq, q, ROWS, INNER, DMODEL, INNER, 0, nullptr);
    sgemm128<<<grid_proj, blk>>>(context, Wkv, k, ROWS, INNER, DMODEL, 2 * INNER, 0, nullptr);
    sgemm128<<<grid_proj, blk>>>(context, Wkv, v, ROWS, INNER, DMODEL, 2 * INNER, INNER, nullptr);

    // attention on tensor cores
    dim3 grid_attn(SEQ / 64, HEADS, BATCH);
    flash_mma<<<grid_attn, 128, FLASH_SMEM>>>(q, k, v, mask, o);

    // out = o @ Wout + bout
    sgemm128<<<grid_proj, blk>>>(o, Wout, out, ROWS, DMODEL, INNER, DMODEL, 0, bout);
}

// round 10
// speedup vs baseline: 2.0645x; 1.1934x over previous
#include <cuda_runtime.h>
#include <cuda_bf16.h>
#include <math.h>
#include <stdint.h>

// Problem constants
#define BATCH   2
#define SEQ     2048
#define DMODEL  1024
#define HEADS   16
#define DHEAD   64
#define INNER   (HEADS*DHEAD)      // 1024
#define ROWS    (BATCH*SEQ)        // 4096
#define ATT_SCALE 0.125f
#define MASK_NEG 1000000.0f

// Scratch (allocation-free rule: static __device__ globals)
__device__ float g_q[ROWS*INNER];
__device__ float g_k[ROWS*INNER];
__device__ float g_v[ROWS*INNER];
__device__ float g_o[ROWS*INNER];

// ---------------------------------------------------------------------------
// mma.sync helpers (compute_103-compatible; NO tcgen05 — harness PTX target
// is compute_103 which rejects arch-specific instructions)
// ---------------------------------------------------------------------------
__device__ __forceinline__ void mma_tf32(float* d, const uint32_t* a,
                                         uint32_t b0, uint32_t b1)
{
    asm volatile(
        "mma.sync.aligned.m16n8k8.row.col.f32.tf32.tf32.f32 "
        "{%0,%1,%2,%3}, {%4,%5,%6,%7}, {%8,%9}, {%0,%1,%2,%3};"
        : "+f"(d[0]), "+f"(d[1]), "+f"(d[2]), "+f"(d[3])
        : "r"(a[0]), "r"(a[1]), "r"(a[2]), "r"(a[3]), "r"(b0), "r"(b1));
}

__device__ __forceinline__ void mma_bf16(float* d, const uint32_t* a,
                                         uint32_t b0, uint32_t b1)
{
    asm volatile(
        "mma.sync.aligned.m16n8k16.row.col.f32.bf16.bf16.f32 "
        "{%0,%1,%2,%3}, {%4,%5,%6,%7}, {%8,%9}, {%0,%1,%2,%3};"
        : "+f"(d[0]), "+f"(d[1]), "+f"(d[2]), "+f"(d[3])
        : "r"(a[0]), "r"(a[1]), "r"(a[2]), "r"(a[3]), "r"(b0), "r"(b1));
}

__device__ __forceinline__ uint32_t f2tf32(float x) {
    uint32_t r; asm("cvt.rna.tf32.f32 %0, %1;" : "=r"(r) : "f"(x)); return r;
}

// pack two floats into bf16x2 (lo_val -> low half, hi_val -> high half)
__device__ __forceinline__ uint32_t pack_bf16x2(float lo_val, float hi_val) {
    uint32_t r;
    asm("cvt.rn.bf16x2.f32 %0, %1, %2;" : "=r"(r) : "f"(hi_val), "f"(lo_val));
    return r;
}

__device__ __forceinline__ void ldmx4t(uint32_t& r0, uint32_t& r1,
                                       uint32_t& r2, uint32_t& r3, uint32_t addr)
{
    asm volatile(
        "ldmatrix.sync.aligned.m8n8.x4.trans.shared.b16 {%0,%1,%2,%3}, [%4];"
        : "=r"(r0), "=r"(r1), "=r"(r2), "=r"(r3) : "r"(addr));
}

__device__ __forceinline__ void cp_async16(uint32_t saddr, const void* gptr) {
    asm volatile("cp.async.cg.shared.global [%0], [%1], 16;"
                 :: "r"(saddr), "l"(gptr));
}
__device__ __forceinline__ void cp_async_commit() {
    asm volatile("cp.async.commit_group;");
}
__device__ __forceinline__ void cp_async_wait0() {
    asm volatile("cp.async.wait_group 0;");
}

// ===========================================================================
// Tensor-core GEMM, tf32 3-term (AhBh + AlBh + AhBl), fp32-level accuracy.
// C[4096 x 1024-slice] = A[4096 x 1024] * B[1024 x N'], B row-major [k][n]
// (W natural layout), tiles: block 128x128, K-chunk 32, 256 thr (8 warps,
// warp = 32m x 64n). cp.async staging -> split-convert -> mma, pipelined.
// Used for q,k projections (precision-critical: masked-row logits quantize
// to 0.0625 fp32 grid; need delta-logit < ~7e-6).
// ===========================================================================
#define T32_AHI  0
#define T32_ALO  18432                   // 128*36*4
#define T32_BHI  36864
#define T32_BLO  54272                   // + 32*136*4
#define T32_STGA 71680
#define T32_STGB 88064
#define T32_SMEM 104448

__global__ __launch_bounds__(256, 1)
void gemm_tf32(const float* __restrict__ A, const float* __restrict__ B,
               float* __restrict__ C, int ldb, int boff,
               const float* __restrict__ bias)
{
    extern __shared__ char smem[];
    float* Ahi = (float*)(smem + T32_AHI);   // [128 m][36 k]
    float* Alo = (float*)(smem + T32_ALO);
    float* Bhi = (float*)(smem + T32_BHI);   // [32 k][136 n]
    float* Blo = (float*)(smem + T32_BLO);
    float* StgA = (float*)(smem + T32_STGA); // [128][32]
    float* StgB = (float*)(smem + T32_STGB); // [32][128]
    const uint32_t sbase = (uint32_t)__cvta_generic_to_shared(smem);

    const int tid = threadIdx.x;
    const int wid = tid >> 5;
    const int lane = tid & 31;
    const int row_a = lane >> 2;
    const int colc  = lane & 3;
    const int m0  = (wid >> 1) * 32;
    const int n0w = (wid & 1) * 64;
    const int rowBase = blockIdx.y * 128;
    const int colBase = blockIdx.x * 128;

    // prefetch chunk 0
    #pragma unroll
    for (int p = 0; p < 4; p++) {
        int idx = tid + p * 256;
        int r = idx >> 3, c4 = (idx & 7) << 2;
        cp_async16(sbase + T32_STGA + (uint32_t)((r * 32 + c4) * 4),
                   A + (long)(rowBase + r) * 1024 + c4);
        int rb = idx >> 5, cb = (idx & 31) << 2;
        cp_async16(sbase + T32_STGB + (uint32_t)((rb * 128 + cb) * 4),
                   B + (long)rb * ldb + boff + colBase + cb);
    }
    cp_async_commit();

    float acc[2][8][4];
    #pragma unroll
    for (int m = 0; m < 2; m++)
        #pragma unroll
        for (int j = 0; j < 8; j++)
            #pragma unroll
            for (int c = 0; c < 4; c++) acc[m][j][c] = 0.f;

    for (int kc = 0; kc < 32; kc++) {
        cp_async_wait0();
        __syncthreads();

        // convert staging -> tf32 hi/lo operands
        #pragma unroll
        for (int p = 0; p < 16; p++) {
            int e = tid + p * 256;
            int r = e >> 5, c = e & 31;
            float v = StgA[e];
            uint32_t hb = f2tf32(v);
            Ahi[r * 36 + c] = __uint_as_float(hb);
            Alo[r * 36 + c] = __uint_as_float(f2tf32(v - __uint_as_float(hb)));
            int rb = e >> 7, cb = e & 127;
            float w = StgB[e];
            uint32_t wb = f2tf32(w);
            Bhi[rb * 136 + cb] = __uint_as_float(wb);
            Blo[rb * 136 + cb] = __uint_as_float(f2tf32(w - __uint_as_float(wb)));
        }
        __syncthreads();

        // prefetch next chunk (overlaps compute)
        if (kc + 1 < 32) {
            int k1 = (kc + 1) * 32;
            #pragma unroll
            for (int p = 0; p < 4; p++) {
                int idx = tid + p * 256;
                int r = idx >> 3, c4 = (idx & 7) << 2;
                cp_async16(sbase + T32_STGA + (uint32_t)((r * 32 + c4) * 4),
                           A + (long)(rowBase + r) * 1024 + k1 + c4);
                int rb = idx >> 5, cb = (idx & 31) << 2;
                cp_async16(sbase + T32_STGB + (uint32_t)((rb * 128 + cb) * 4),
                           B + (long)(k1 + rb) * ldb + boff + colBase + cb);
            }
            cp_async_commit();
        }

        // MMAs: 4 k-steps of 8
        #pragma unroll
        for (int s = 0; s < 4; s++) {
            const int kb = s * 8;
            uint32_t ah0[4], al0[4], ah1[4], al1[4];
            #pragma unroll
            for (int i = 0; i < 4; i++) {
                int rr = m0 + row_a + ((i & 1) << 3);
                int kk = kb + colc + ((i >> 1) << 2);
                ah0[i] = __float_as_uint(Ahi[rr * 36 + kk]);
                al0[i] = __float_as_uint(Alo[rr * 36 + kk]);
                ah1[i] = __float_as_uint(Ahi[(rr + 16) * 36 + kk]);
                al1[i] = __float_as_uint(Alo[(rr + 16) * 36 + kk]);
            }
            #pragma unroll
            for (int j = 0; j < 8; j++) {
                int nc = n0w + j * 8 + row_a;
                int i0 = (kb + colc) * 136 + nc;
                int i1 = (kb + colc + 4) * 136 + nc;
                uint32_t bh0 = __float_as_uint(Bhi[i0]);
                uint32_t bh1 = __float_as_uint(Bhi[i1]);
                uint32_t bl0 = __float_as_uint(Blo[i0]);
                uint32_t bl1 = __float_as_uint(Blo[i1]);
                mma_tf32(acc[0][j], ah0, bh0, bh1);
                mma_tf32(acc[0][j], al0, bh0, bh1);
                mma_tf32(acc[0][j], ah0, bl0, bl1);
                mma_tf32(acc[1][j], ah1, bh0, bh1);
                mma_tf32(acc[1][j], al1, bh0, bh1);
                mma_tf32(acc[1][j], ah1, bl0, bl1);
            }
        }
        __syncthreads();
    }

    // epilogue
    #pragma unroll
    for (int j = 0; j < 8; j++) {
        int col = colBase + n0w + j * 8 + 2 * colc;
        float bx = bias ? bias[col] : 0.f;
        float by = bias ? bias[col + 1] : 0.f;
        #pragma unroll
        for (int m = 0; m < 2; m++) {
            int row = rowBase + m0 + m * 16 + row_a;
            *(float2*)(C + (long)row * 1024 + col) =
                make_float2(acc[m][j][0] + bx, acc[m][j][1] + by);
            *(float2*)(C + (long)(row + 8) * 1024 + col) =
                make_float2(acc[m][j][2] + bx, acc[m][j][3] + by);
        }
    }
}

// ===========================================================================
// Tensor-core GEMM, bf16 3-term (error ~1.5e-5) — for v and out projections
// (not precision-critical). Same structure; B frags via ldmatrix.x4.trans.
// ===========================================================================
#define B16_AHI  0
#define B16_ALO  10240                   // 128*40*2
#define B16_BHI  20480
#define B16_BLO  29184                   // + 32*136*2
#define B16_STGA 37888
#define B16_STGB 54272
#define B16_SMEM 70656

__global__ __launch_bounds__(256, 1)
void gemm_bf16(const float* __restrict__ A, const float* __restrict__ B,
               float* __restrict__ C, int ldb, int boff,
               const float* __restrict__ bias)
{
    extern __shared__ char smem[];
    __nv_bfloat16* Ahi = (__nv_bfloat16*)(smem + B16_AHI);   // [128 m][40 k]
    __nv_bfloat16* Alo = (__nv_bfloat16*)(smem + B16_ALO);
    __nv_bfloat16* Bhi = (__nv_bfloat16*)(smem + B16_BHI);   // [32 k][136 n]
    __nv_bfloat16* Blo = (__nv_bfloat16*)(smem + B16_BLO);
    float* StgA = (float*)(smem + B16_STGA);
    float* StgB = (float*)(smem + B16_STGB);
    const uint32_t sbase = (uint32_t)__cvta_generic_to_shared(smem);

    const int tid = threadIdx.x;
    const int wid = tid >> 5;
    const int lane = tid & 31;
    const int row_a = lane >> 2;
    const int colc  = lane & 3;
    const int lm_k = lane & 15;
    const int lm_d = (lane >> 4) * 8;
    const int m0  = (wid >> 1) * 32;
    const int n0w = (wid & 1) * 64;
    const int rowBase = blockIdx.y * 128;
    const int colBase = blockIdx.x * 128;
    const uint32_t bhi_base = sbase + B16_BHI;
    const uint32_t blo_base = sbase + B16_BLO;

    #pragma unroll
    for (int p = 0; p < 4; p++) {
        int idx = tid + p * 256;
        int r = idx >> 3, c4 = (idx & 7) << 2;
        cp_async16(sbase + B16_STGA + (uint32_t)((r * 32 + c4) * 4),
                   A + (long)(rowBase + r) * 1024 + c4);
        int rb = idx >> 5, cb = (idx & 31) << 2;
        cp_async16(sbase + B16_STGB + (uint32_t)((rb * 128 + cb) * 4),
                   B + (long)rb * ldb + boff + colBase + cb);
    }
    cp_async_commit();

    float acc[2][8][4];
    #pragma unroll
    for (int m = 0; m < 2; m++)
        #pragma unroll
        for (int j = 0; j < 8; j++)
            #pragma unroll
            for (int c = 0; c < 4; c++) acc[m][j][c] = 0.f;

    for (int kc = 0; kc < 32; kc++) {
        cp_async_wait0();
        __syncthreads();

        // convert staging -> bf16 hi/lo pairs
        #pragma unroll
        for (int p = 0; p < 8; p++) {
            int e2 = tid + p * 256;              // pair index (2048 pairs)
            int r = e2 >> 4, cp2 = (e2 & 15) << 1;
            float v0 = StgA[r * 32 + cp2], v1 = StgA[r * 32 + cp2 + 1];
            uint32_t hh = pack_bf16x2(v0, v1);
            *(uint32_t*)&Ahi[r * 40 + cp2] = hh;
            *(uint32_t*)&Alo[r * 40 + cp2] =
                pack_bf16x2(v0 - __uint_as_float(hh << 16),
                            v1 - __uint_as_float(hh & 0xFFFF0000u));
            int rb = e2 >> 6, cb = (e2 & 63) << 1;
            float w0 = StgB[rb * 128 + cb], w1 = StgB[rb * 128 + cb + 1];
            uint32_t wh = pack_bf16x2(w0, w1);
            *(uint32_t*)&Bhi[rb * 136 + cb] = wh;
            *(uint32_t*)&Blo[rb * 136 + cb] =
                pack_bf16x2(w0 - __uint_as_float(wh << 16),
                            w1 - __uint_as_float(wh & 0xFFFF0000u));
        }
        __syncthreads();

        if (kc + 1 < 32) {
            int k1 = (kc + 1) * 32;
            #pragma unroll
            for (int p = 0; p < 4; p++) {
                int idx = tid + p * 256;
                int r = idx >> 3, c4 = (idx & 7) << 2;
                cp_async16(sbase + B16_STGA + (uint32_t)((r * 32 + c4) * 4),
                           A + (long)(rowBase + r) * 1024 + k1 + c4);
                int rb = idx >> 5, cb = (idx & 31) << 2;
                cp_async16(sbase + B16_STGB + (uint32_t)((rb * 128 + cb) * 4),
                           B + (long)(k1 + rb) * ldb + boff + colBase + cb);
            }
            cp_async_commit();
        }

        // MMAs: 2 k-steps of 16
        #pragma unroll
        for (int s = 0; s < 2; s++) {
            const int kb = s * 16;
            uint32_t ah0[4], al0[4], ah1[4], al1[4];
            #pragma unroll
            for (int i = 0; i < 4; i++) {
                int rr = m0 + row_a + ((i & 1) << 3);
                int kk = kb + 2 * colc + ((i >> 1) << 3);
                ah0[i] = *(const uint32_t*)&Ahi[rr * 40 + kk];
                al0[i] = *(const uint32_t*)&Alo[rr * 40 + kk];
                ah1[i] = *(const uint32_t*)&Ahi[(rr + 16) * 40 + kk];
                al1[i] = *(const uint32_t*)&Alo[(rr + 16) * 40 + kk];
            }
            #pragma unroll
            for (int j2 = 0; j2 < 4; j2++) {
                uint32_t off =
                    (uint32_t)(((kb + lm_k) * 136 + n0w + j2 * 16 + lm_d) * 2);
                uint32_t h0, h1, h2, h3, l0, l1, l2, l3;
                ldmx4t(h0, h1, h2, h3, bhi_base + off);
                ldmx4t(l0, l1, l2, l3, blo_base + off);
                int jn = j2 * 2;
                mma_bf16(acc[0][jn], ah0, h0, h1);
                mma_bf16(acc[0][jn], al0, h0, h1);
                mma_bf16(acc[0][jn], ah0, l0, l1);
                mma_bf16(acc[1][jn], ah1, h0, h1);
                mma_bf16(acc[1][jn], al1, h0, h1);
                mma_bf16(acc[1][jn], ah1, l0, l1);
                mma_bf16(acc[0][jn+1], ah0, h2, h3);
                mma_bf16(acc[0][jn+1], al0, h2, h3);
                mma_bf16(acc[0][jn+1], ah0, l2, l3);
                mma_bf16(acc[1][jn+1], ah1, h2, h3);
                mma_bf16(acc[1][jn+1], al1, h2, h3);
                mma_bf16(acc[1][jn+1], ah1, l2, l3);
            }
        }
        __syncthreads();
    }

    #pragma unroll
    for (int j = 0; j < 8; j++) {
        int col = colBase + n0w + j * 8 + 2 * colc;
        float bx = bias ? bias[col] : 0.f;
        float by = bias ? bias[col + 1] : 0.f;
        #pragma unroll
        for (int m = 0; m < 2; m++) {
            int row = rowBase + m0 + m * 16 + row_a;
            *(float2*)(C + (long)row * 1024 + col) =
                make_float2(acc[m][j][0] + bx, acc[m][j][1] + by);
            *(float2*)(C + (long)(row + 8) * 1024 + col) =
                make_float2(acc[m][j][2] + bx, acc[m][j][3] + by);
        }
    }
}

// ---------------------------------------------------------------------------
// Flash attention v3 (unchanged from R9 — passed, rel_err 1.278e-4)
// ---------------------------------------------------------------------------
#define KT_HI   0
#define KT_LO   18432
#define V_HI    36864
#define V_LO    46080
#define STG_K   55296
#define STG_V   71680
#define FLASH_SMEM 88064

__global__ __launch_bounds__(128, 2)
void flash_mma(const float* __restrict__ Q, const float* __restrict__ K,
               const float* __restrict__ V, const int* __restrict__ mask,
               float* __restrict__ O)
{
    extern __shared__ char smem[];
    float* KtHi = (float*)(smem + KT_HI);
    float* KtLo = (float*)(smem + KT_LO);
    __nv_bfloat16* VHi = (__nv_bfloat16*)(smem + V_HI);
    __nv_bfloat16* VLo = (__nv_bfloat16*)(smem + V_LO);
    float* StgK = (float*)(smem + STG_K);
    float* StgV = (float*)(smem + STG_V);

    const uint32_t sbase = (uint32_t)__cvta_generic_to_shared(smem);

    const int b  = blockIdx.z;
    const int h  = blockIdx.y;
    const int n0 = blockIdx.x * 64;

    const int tid   = threadIdx.x;
    const int wid   = tid >> 5;
    const int lane  = tid & 31;
    const int r0    = wid * 16;
    const int row_a = lane >> 2;
    const int colc  = lane & 3;

    const long baseQ = (long)b * SEQ * DMODEL + (long)h * DHEAD;

    const int lm_k = lane & 15;
    const int lm_d = (lane >> 4) * 8;
    const uint32_t vhi_base = sbase + V_HI;
    const uint32_t vlo_base = sbase + V_LO;

    const int sg_r = tid >> 4;
    const int sg_c = (tid & 15) << 2;

    {
        #pragma unroll
        for (int p = 0; p < 8; p++) {
            int r = sg_r + p * 8;
            uint32_t so = (uint32_t)((r * 64 + sg_c) * 4);
            cp_async16(sbase + STG_K + so, K + baseQ + (long)r * DMODEL + sg_c);
            cp_async16(sbase + STG_V + so, V + baseQ + (long)r * DMODEL + sg_c);
        }
        cp_async_commit();
    }

    uint32_t qh[32], ql[32];
    #pragma unroll
    for (int s = 0; s < 8; s++) {
        #pragma unroll
        for (int i = 0; i < 4; i++) {
            int rr = n0 + r0 + row_a + ((i & 1) << 3);
            int kk = (s << 3) + colc + ((i >> 1) << 2);
            float qv = Q[baseQ + (long)rr * DMODEL + kk];
            uint32_t hb = f2tf32(qv);
            qh[s*4 + i] = hb;
            ql[s*4 + i] = f2tf32(qv - __uint_as_float(hb));
        }
    }

    const float pen0 = (1.0f - (float)mask[b*SEQ + n0 + r0 + row_a])     * MASK_NEG;
    const float pen1 = (1.0f - (float)mask[b*SEQ + n0 + r0 + row_a + 8]) * MASK_NEG;

    float Oacc[32];
    #pragma unroll
    for (int i = 0; i < 32; i++) Oacc[i] = 0.f;
    float mstat[2] = {-1e30f, -1e30f};
    float lstat[2] = {0.f, 0.f};

    cp_async_wait0();
    __syncthreads();

    for (int kt = 0; kt < SEQ / 64; kt++) {
        #pragma unroll
        for (int p = 0; p < 8; p++) {
            int r = sg_r + p * 8;
            int c = sg_c;
            float4 kv = *(const float4*)(StgK + r * 64 + c);
            float4 vv = *(const float4*)(StgV + r * 64 + c);
            float kf[4] = {kv.x, kv.y, kv.z, kv.w};
            #pragma unroll
            for (int i = 0; i < 4; i++) {
                int d = c + i;
                uint32_t hb = f2tf32(kf[i]);
                int idx = d * 72 + (r ^ (d >> 2));
                KtHi[idx] = __uint_as_float(hb);
                KtLo[idx] = __uint_as_float(f2tf32(kf[i] - __uint_as_float(hb)));
            }
            uint2 ph, pl;
            ph.x = pack_bf16x2(vv.x, vv.y);
            ph.y = pack_bf16x2(vv.z, vv.w);
            pl.x = pack_bf16x2(vv.x - __uint_as_float(ph.x << 16),
                               vv.y - __uint_as_float(ph.x & 0xFFFF0000u));
            pl.y = pack_bf16x2(vv.z - __uint_as_float(ph.y << 16),
                               vv.w - __uint_as_float(ph.y & 0xFFFF0000u));
            *(uint2*)&VHi[r * 72 + c] = ph;
            *(uint2*)&VLo[r * 72 + c] = pl;
        }
        __syncthreads();

        if (kt + 1 < SEQ / 64) {
            const int m1 = (kt + 1) * 64;
            #pragma unroll
            for (int p = 0; p < 8; p++) {
                int r = sg_r + p * 8;
                uint32_t so = (uint32_t)((r * 64 + sg_c) * 4);
                cp_async16(sbase + STG_K + so, K + baseQ + (long)(m1 + r) * DMODEL + sg_c);
                cp_async16(sbase + STG_V + so, V + baseQ + (long)(m1 + r) * DMODEL + sg_c);
            }
            cp_async_commit();
        }

        float S[32];
        #pragma unroll
        for (int i = 0; i < 32; i++) S[i] = 0.f;

        #pragma unroll
        for (int s = 0; s < 8; s++) {
            const int x0 = 2 * s;
            const int x1 = 2 * s + 1;
            const int rb0 = (s * 8 + colc) * 72;
            const int rb1 = (s * 8 + colc + 4) * 72;
            #pragma unroll
            for (int j = 0; j < 8; j++) {
                int key  = j * 8 + row_a;
                int i0   = rb0 + (key ^ x0);
                int i1   = rb1 + (key ^ x1);
                uint32_t bh0 = __float_as_uint(KtHi[i0]);
                uint32_t bh1 = __float_as_uint(KtHi[i1]);
                uint32_t bl0 = __float_as_uint(KtLo[i0]);
                uint32_t bl1 = __float_as_uint(KtLo[i1]);
                mma_tf32(&S[j*4], &qh[s*4], bh0, bh1);
                mma_tf32(&S[j*4], &ql[s*4], bh0, bh1);
                mma_tf32(&S[j*4], &qh[s*4], bl0, bl1);
            }
        }

        #pragma unroll
        for (int t = 0; t < 2; t++) {
            float pent = t ? pen1 : pen0;
            float mloc = -1e30f;
            #pragma unroll
            for (int j = 0; j < 8; j++) {
                float v0 = S[j*4 + 2*t]     * ATT_SCALE - pent;
                float v1 = S[j*4 + 2*t + 1] * ATT_SCALE - pent;
                S[j*4 + 2*t]     = v0;
                S[j*4 + 2*t + 1] = v1;
                mloc = fmaxf(mloc, fmaxf(v0, v1));
            }
            mloc = fmaxf(mloc, __shfl_xor_sync(0xffffffffu, mloc, 1));
            mloc = fmaxf(mloc, __shfl_xor_sync(0xffffffffu, mloc, 2));
            float mnew  = fmaxf(mstat[t], mloc);
            float alpha = __expf(mstat[t] - mnew);
            float lloc = 0.f;
            #pragma unroll
            for (int j = 0; j < 8; j++) {
                float p0 = __expf(S[j*4 + 2*t]     - mnew);
                float p1 = __expf(S[j*4 + 2*t + 1] - mnew);
                S[j*4 + 2*t]     = p0;
                S[j*4 + 2*t + 1] = p1;
                lloc += p0 + p1;
            }
            lloc += __shfl_xor_sync(0xffffffffu, lloc, 1);
            lloc += __shfl_xor_sync(0xffffffffu, lloc, 2);
            lstat[t] = lstat[t] * alpha + lloc;
            mstat[t] = mnew;
            #pragma unroll
            for (int j = 0; j < 8; j++) {
                Oacc[j*4 + 2*t]     *= alpha;
                Oacc[j*4 + 2*t + 1] *= alpha;
            }
        }

        #pragma unroll
        for (int t2 = 0; t2 < 4; t2++) {
            uint32_t ah[4], al[4];
            #pragma unroll
            for (int i = 0; i < 4; i++) {
                int jt  = 2*t2 + (i >> 1);
                int off = (i & 1) * 2;
                float p0 = S[jt*4 + off];
                float p1 = S[jt*4 + off + 1];
                uint32_t hh = pack_bf16x2(p0, p1);
                ah[i] = hh;
                al[i] = pack_bf16x2(p0 - __uint_as_float(hh << 16),
                                    p1 - __uint_as_float(hh & 0xFFFF0000u));
            }
            const uint32_t row_off =
                (uint32_t)(((t2 * 16 + lm_k) * 72 + lm_d) * 2);
            #pragma unroll
            for (int j2 = 0; j2 < 4; j2++) {
                uint32_t off = row_off + (uint32_t)(j2 * 16 * 2);
                uint32_t h0, h1, h2, h3, l0, l1, l2, l3;
                ldmx4t(h0, h1, h2, h3, vhi_base + off);
                ldmx4t(l0, l1, l2, l3, vlo_base + off);
                mma_bf16(&Oacc[(2*j2)*4], ah, h0, h1);
                mma_bf16(&Oacc[(2*j2)*4], al, h0, h1);
                mma_bf16(&Oacc[(2*j2)*4], ah, l0, l1);
                mma_bf16(&Oacc[(2*j2+1)*4], ah, h2, h3);
                mma_bf16(&Oacc[(2*j2+1)*4], al, h2, h3);
                mma_bf16(&Oacc[(2*j2+1)*4], ah, l2, l3);
            }
        }

        if (kt + 1 < SEQ / 64) cp_async_wait0();
        __syncthreads();
    }

    float inv0 = 1.f / lstat[0];
    float inv1 = 1.f / lstat[1];
    int rowg = n0 + r0 + row_a;
    #pragma unroll
    for (int j = 0; j < 8; j++) {
        float2 v0 = make_float2(Oacc[j*4 + 0] * inv0, Oacc[j*4 + 1] * inv0);
        float2 v1 = make_float2(Oacc[j*4 + 2] * inv1, Oacc[j*4 + 3] * inv1);
        *(float2*)(O + baseQ + (long)rowg       * DMODEL + j*8 + 2*colc) = v0;
        *(float2*)(O + baseQ + (long)(rowg + 8) * DMODEL + j*8 + 2*colc) = v1;
    }
}

// ---------------------------------------------------------------------------
// Launch
// ---------------------------------------------------------------------------
extern "C" void kernel_launch(void* const* d_in, const int* in_sizes, int n_in,
                              void* d_out, int out_size)
{
    const float* x       = (const float*)d_in[0];
    const float* context = (const float*)d_in[1];
    const int*   mask    = (const int*)d_in[2];
    const float* Wq      = (const float*)d_in[3];
    const float* Wkv     = (const float*)d_in[4];
    const float* Wout    = (const float*)d_in[5];
    const float* bout    = (const float*)d_in[6];
    float* out = (float*)d_out;

    float *q, *k, *v, *o;
    cudaGetSymbolAddress((void**)&q, g_q);
    cudaGetSymbolAddress((void**)&k, g_k);
    cudaGetSymbolAddress((void**)&v, g_v);
    cudaGetSymbolAddress((void**)&o, g_o);

    cudaFuncSetAttribute(flash_mma,
                         cudaFuncAttributeMaxDynamicSharedMemorySize, FLASH_SMEM);
    cudaFuncSetAttribute(gemm_tf32,
                         cudaFuncAttributeMaxDynamicSharedMemorySize, T32_SMEM);
    cudaFuncSetAttribute(gemm_bf16,
                         cudaFuncAttributeMaxDynamicSharedMemorySize, B16_SMEM);

    dim3 gg(1024 / 128, 4096 / 128);   // (8, 32)

    // q = x @ Wq ; k = context @ Wkv[:, :1024]  (tf32 3-term: fp32-accurate)
    gemm_tf32<<<gg, 256, T32_SMEM>>>(x, Wq, q, INNER, 0, nullptr);
    gemm_tf32<<<gg, 256, T32_SMEM>>>(context, Wkv, k, 2 * INNER, 0, nullptr);
    // v = context @ Wkv[:, 1024:]  (bf16 3-term — not flip-sensitive)
    gemm_bf16<<<gg, 256, B16_SMEM>>>(context, Wkv, v, 2 * INNER, INNER, nullptr);

    // attention on tensor cores
    dim3 grid_attn(SEQ / 64, HEADS, BATCH);
    flash_mma<<<grid_attn, 128, FLASH_SMEM>>>(q, k, v, mask, o);

    // out = o @ Wout + bout  (bf16 3-term)
    gemm_bf16<<<gg, 256, B16_SMEM>>>(o, Wout, out, INNER, 0, bout);
}

// round 11
// speedup vs baseline: 2.4538x; 1.1886x over previous
#include <cuda_runtime.h>
#include <cuda_bf16.h>
#include <cuda_fp16.h>
#include <math.h>
#include <stdint.h>

// Problem constants
#define BATCH   2
#define SEQ     2048
#define DMODEL  1024
#define HEADS   16
#define DHEAD   64
#define INNER   (HEADS*DHEAD)      // 1024
#define ROWS    (BATCH*SEQ)        // 4096
#define ATT_SCALE 0.125f
#define MASK_NEG 1000000.0f

// Scratch (allocation-free rule: static __device__ globals)
__device__ float g_q[ROWS*INNER];
__device__ float g_k[ROWS*INNER];
__device__ float g_v[ROWS*INNER];
__device__ float g_o[ROWS*INNER];
// pre-converted attention operands, per-head layout [b][h][key][64]
__device__ __half        g_kh[ROWS*INNER];   // fp16 hi
__device__ __half        g_kl[ROWS*INNER];   // fp16 (lo * 2048)
__device__ __nv_bfloat16 g_vh[ROWS*INNER];
__device__ __nv_bfloat16 g_vl[ROWS*INNER];

// ---------------------------------------------------------------------------
// mma.sync helpers (compute_103-compatible; NO tcgen05)
// ---------------------------------------------------------------------------
__device__ __forceinline__ void mma_tf32(float* d, const uint32_t* a,
                                         uint32_t b0, uint32_t b1)
{
    asm volatile(
        "mma.sync.aligned.m16n8k8.row.col.f32.tf32.tf32.f32 "
        "{%0,%1,%2,%3}, {%4,%5,%6,%7}, {%8,%9}, {%0,%1,%2,%3};"
        : "+f"(d[0]), "+f"(d[1]), "+f"(d[2]), "+f"(d[3])
        : "r"(a[0]), "r"(a[1]), "r"(a[2]), "r"(a[3]), "r"(b0), "r"(b1));
}

__device__ __forceinline__ void mma_bf16(float* d, const uint32_t* a,
                                         uint32_t b0, uint32_t b1)
{
    asm volatile(
        "mma.sync.aligned.m16n8k16.row.col.f32.bf16.bf16.f32 "
        "{%0,%1,%2,%3}, {%4,%5,%6,%7}, {%8,%9}, {%0,%1,%2,%3};"
        : "+f"(d[0]), "+f"(d[1]), "+f"(d[2]), "+f"(d[3])
        : "r"(a[0]), "r"(a[1]), "r"(a[2]), "r"(a[3]), "r"(b0), "r"(b1));
}

__device__ __forceinline__ void mma_fp16(float* d, const uint32_t* a,
                                         uint32_t b0, uint32_t b1)
{
    asm volatile(
        "mma.sync.aligned.m16n8k16.row.col.f32.f16.f16.f32 "
        "{%0,%1,%2,%3}, {%4,%5,%6,%7}, {%8,%9}, {%0,%1,%2,%3};"
        : "+f"(d[0]), "+f"(d[1]), "+f"(d[2]), "+f"(d[3])
        : "r"(a[0]), "r"(a[1]), "r"(a[2]), "r"(a[3]), "r"(b0), "r"(b1));
}

__device__ __forceinline__ uint32_t f2tf32(float x) {
    uint32_t r; asm("cvt.rna.tf32.f32 %0, %1;" : "=r"(r) : "f"(x)); return r;
}

__device__ __forceinline__ uint32_t pack_bf16x2(float lo_val, float hi_val) {
    uint32_t r;
    asm("cvt.rn.bf16x2.f32 %0, %1, %2;" : "=r"(r) : "f"(hi_val), "f"(lo_val));
    return r;
}

__device__ __forceinline__ uint32_t pack_f16x2(float lo_val, float hi_val) {
    __half h0 = __float2half_rn(lo_val);
    __half h1 = __float2half_rn(hi_val);
    return ((uint32_t)__half_as_ushort(h1) << 16) | __half_as_ushort(h0);
}

// ldmatrix x4, transposed (b16) — for V (k = key contiguous-in-rows)
__device__ __forceinline__ void ldmx4t(uint32_t& r0, uint32_t& r1,
                                       uint32_t& r2, uint32_t& r3, uint32_t addr)
{
    asm volatile(
        "ldmatrix.sync.aligned.m8n8.x4.trans.shared.b16 {%0,%1,%2,%3}, [%4];"
        : "=r"(r0), "=r"(r1), "=r"(r2), "=r"(r3) : "r"(addr));
}
// ldmatrix x4, non-transposed — for K as QK's B operand ([key][d], d = k dim)
__device__ __forceinline__ void ldmx4(uint32_t& r0, uint32_t& r1,
                                      uint32_t& r2, uint32_t& r3, uint32_t addr)
{
    asm volatile(
        "ldmatrix.sync.aligned.m8n8.x4.shared.b16 {%0,%1,%2,%3}, [%4];"
        : "=r"(r0), "=r"(r1), "=r"(r2), "=r"(r3) : "r"(addr));
}

__device__ __forceinline__ void cp_async16(uint32_t saddr, const void* gptr) {
    asm volatile("cp.async.cg.shared.global [%0], [%1], 16;"
                 :: "r"(saddr), "l"(gptr));
}
__device__ __forceinline__ void cp_async_commit() {
    asm volatile("cp.async.commit_group;");
}
__device__ __forceinline__ void cp_async_wait0() {
    asm volatile("cp.async.wait_group 0;");
}

// ===========================================================================
// GEMM tf32 3-term (unchanged from R10 — q,k projections, fp32-level)
// ===========================================================================
#define T32_AHI  0
#define T32_ALO  18432
#define T32_BHI  36864
#define T32_BLO  54272
#define T32_STGA 71680
#define T32_STGB 88064
#define T32_SMEM 104448

__global__ __launch_bounds__(256, 1)
void gemm_tf32(const float* __restrict__ A, const float* __restrict__ B,
               float* __restrict__ C, int ldb, int boff,
               const float* __restrict__ bias)
{
    extern __shared__ char smem[];
    float* Ahi = (float*)(smem + T32_AHI);
    float* Alo = (float*)(smem + T32_ALO);
    float* Bhi = (float*)(smem + T32_BHI);
    float* Blo = (float*)(smem + T32_BLO);
    float* StgA = (float*)(smem + T32_STGA);
    float* StgB = (float*)(smem + T32_STGB);
    const uint32_t sbase = (uint32_t)__cvta_generic_to_shared(smem);

    const int tid = threadIdx.x;
    const int wid = tid >> 5;
    const int lane = tid & 31;
    const int row_a = lane >> 2;
    const int colc  = lane & 3;
    const int m0  = (wid >> 1) * 32;
    const int n0w = (wid & 1) * 64;
    const int rowBase = blockIdx.y * 128;
    const int colBase = blockIdx.x * 128;

    #pragma unroll
    for (int p = 0; p < 4; p++) {
        int idx = tid + p * 256;
        int r = idx >> 3, c4 = (idx & 7) << 2;
        cp_async16(sbase + T32_STGA + (uint32_t)((r * 32 + c4) * 4),
                   A + (long)(rowBase + r) * 1024 + c4);
        int rb = idx >> 5, cb = (idx & 31) << 2;
        cp_async16(sbase + T32_STGB + (uint32_t)((rb * 128 + cb) * 4),
                   B + (long)rb * ldb + boff + colBase + cb);
    }
    cp_async_commit();

    float acc[2][8][4];
    #pragma unroll
    for (int m = 0; m < 2; m++)
        #pragma unroll
        for (int j = 0; j < 8; j++)
            #pragma unroll
            for (int c = 0; c < 4; c++) acc[m][j][c] = 0.f;

    for (int kc = 0; kc < 32; kc++) {
        cp_async_wait0();
        __syncthreads();

        #pragma unroll
        for (int p = 0; p < 16; p++) {
            int e = tid + p * 256;
            int r = e >> 5, c = e & 31;
            float v = StgA[e];
            uint32_t hb = f2tf32(v);
            Ahi[r * 36 + c] = __uint_as_float(hb);
            Alo[r * 36 + c] = __uint_as_float(f2tf32(v - __uint_as_float(hb)));
            int rb = e >> 7, cb = e & 127;
            float w = StgB[e];
            uint32_t wb = f2tf32(w);
            Bhi[rb * 136 + cb] = __uint_as_float(wb);
            Blo[rb * 136 + cb] = __uint_as_float(f2tf32(w - __uint_as_float(wb)));
        }
        __syncthreads();

        if (kc + 1 < 32) {
            int k1 = (kc + 1) * 32;
            #pragma unroll
            for (int p = 0; p < 4; p++) {
                int idx = tid + p * 256;
                int r = idx >> 3, c4 = (idx & 7) << 2;
                cp_async16(sbase + T32_STGA + (uint32_t)((r * 32 + c4) * 4),
                           A + (long)(rowBase + r) * 1024 + k1 + c4);
                int rb = idx >> 5, cb = (idx & 31) << 2;
                cp_async16(sbase + T32_STGB + (uint32_t)((rb * 128 + cb) * 4),
                           B + (long)(k1 + rb) * ldb + boff + colBase + cb);
            }
            cp_async_commit();
        }

        #pragma unroll
        for (int s = 0; s < 4; s++) {
            const int kb = s * 8;
            uint32_t ah0[4], al0[4], ah1[4], al1[4];
            #pragma unroll
            for (int i = 0; i < 4; i++) {
                int rr = m0 + row_a + ((i & 1) << 3);
                int kk = kb + colc + ((i >> 1) << 2);
                ah0[i] = __float_as_uint(Ahi[rr * 36 + kk]);
                al0[i] = __float_as_uint(Alo[rr * 36 + kk]);
                ah1[i] = __float_as_uint(Ahi[(rr + 16) * 36 + kk]);
                al1[i] = __float_as_uint(Alo[(rr + 16) * 36 + kk]);
            }
            #pragma unroll
            for (int j = 0; j < 8; j++) {
                int nc = n0w + j * 8 + row_a;
                int i0 = (kb + colc) * 136 + nc;
                int i1 = (kb + colc + 4) * 136 + nc;
                uint32_t bh0 = __float_as_uint(Bhi[i0]);
                uint32_t bh1 = __float_as_uint(Bhi[i1]);
                uint32_t bl0 = __float_as_uint(Blo[i0]);
                uint32_t bl1 = __float_as_uint(Blo[i1]);
                mma_tf32(acc[0][j], ah0, bh0, bh1);
                mma_tf32(acc[0][j], al0, bh0, bh1);
                mma_tf32(acc[0][j], ah0, bl0, bl1);
                mma_tf32(acc[1][j], ah1, bh0, bh1);
                mma_tf32(acc[1][j], al1, bh0, bh1);
                mma_tf32(acc[1][j], ah1, bl0, bl1);
            }
        }
        __syncthreads();
    }

    #pragma unroll
    for (int j = 0; j < 8; j++) {
        int col = colBase + n0w + j * 8 + 2 * colc;
        float bx = bias ? bias[col] : 0.f;
        float by = bias ? bias[col + 1] : 0.f;
        #pragma unroll
        for (int m = 0; m < 2; m++) {
            int row = rowBase + m0 + m * 16 + row_a;
            *(float2*)(C + (long)row * 1024 + col) =
                make_float2(acc[m][j][0] + bx, acc[m][j][1] + by);
            *(float2*)(C + (long)(row + 8) * 1024 + col) =
                make_float2(acc[m][j][2] + bx, acc[m][j][3] + by);
        }
    }
}

// ===========================================================================
// GEMM bf16 3-term (unchanged from R10 — v, out projections)
// ===========================================================================
#define B16_AHI  0
#define B16_ALO  10240
#define B16_BHI  20480
#define B16_BLO  29184
#define B16_STGA 37888
#define B16_STGB 54272
#define B16_SMEM 70656

__global__ __launch_bounds__(256, 1)
void gemm_bf16(const float* __restrict__ A, const float* __restrict__ B,
               float* __restrict__ C, int ldb, int boff,
               const float* __restrict__ bias)
{
    extern __shared__ char smem[];
    __nv_bfloat16* Ahi = (__nv_bfloat16*)(smem + B16_AHI);
    __nv_bfloat16* Alo = (__nv_bfloat16*)(smem + B16_ALO);
    __nv_bfloat16* Bhi = (__nv_bfloat16*)(smem + B16_BHI);
    __nv_bfloat16* Blo = (__nv_bfloat16*)(smem + B16_BLO);
    float* StgA = (float*)(smem + B16_STGA);
    float* StgB = (float*)(smem + B16_STGB);
    const uint32_t sbase = (uint32_t)__cvta_generic_to_shared(smem);

    const int tid = threadIdx.x;
    const int wid = tid >> 5;
    const int lane = tid & 31;
    const int row_a = lane >> 2;
    const int colc  = lane & 3;
    const int lm_k = lane & 15;
    const int lm_d = (lane >> 4) * 8;
    const int m0  = (wid >> 1) * 32;
    const int n0w = (wid & 1) * 64;
    const int rowBase = blockIdx.y * 128;
    const int colBase = blockIdx.x * 128;
    const uint32_t bhi_base = sbase + B16_BHI;
    const uint32_t blo_base = sbase + B16_BLO;

    #pragma unroll
    for (int p = 0; p < 4; p++) {
        int idx = tid + p * 256;
        int r = idx >> 3, c4 = (idx & 7) << 2;
        cp_async16(sbase + B16_STGA + (uint32_t)((r * 32 + c4) * 4),
                   A + (long)(rowBase + r) * 1024 + c4);
        int rb = idx >> 5, cb = (idx & 31) << 2;
        cp_async16(sbase + B16_STGB + (uint32_t)((rb * 128 + cb) * 4),
                   B + (long)rb * ldb + boff + colBase + cb);
    }
    cp_async_commit();

    float acc[2][8][4];
    #pragma unroll
    for (int m = 0; m < 2; m++)
        #pragma unroll
        for (int j = 0; j < 8; j++)
            #pragma unroll
            for (int c = 0; c < 4; c++) acc[m][j][c] = 0.f;

    for (int kc = 0; kc < 32; kc++) {
        cp_async_wait0();
        __syncthreads();

        #pragma unroll
        for (int p = 0; p < 8; p++) {
            int e2 = tid + p * 256;
            int r = e2 >> 4, cp2 = (e2 & 15) << 1;
            float v0 = StgA[r * 32 + cp2], v1 = StgA[r * 32 + cp2 + 1];
            uint32_t hh = pack_bf16x2(v0, v1);
            *(uint32_t*)&Ahi[r * 40 + cp2] = hh;
            *(uint32_t*)&Alo[r * 40 + cp2] =
                pack_bf16x2(v0 - __uint_as_float(hh << 16),
                            v1 - __uint_as_float(hh & 0xFFFF0000u));
            int rb = e2 >> 6, cb = (e2 & 63) << 1;
            float w0 = StgB[rb * 128 + cb], w1 = StgB[rb * 128 + cb + 1];
            uint32_t wh = pack_bf16x2(w0, w1);
            *(uint32_t*)&Bhi[rb * 136 + cb] = wh;
            *(uint32_t*)&Blo[rb * 136 + cb] =
                pack_bf16x2(w0 - __uint_as_float(wh << 16),
                            w1 - __uint_as_float(wh & 0xFFFF0000u));
        }
        __syncthreads();

        if (kc + 1 < 32) {
            int k1 = (kc + 1) * 32;
            #pragma unroll
            for (int p = 0; p < 4; p++) {
                int idx = tid + p * 256;
                int r = idx >> 3, c4 = (idx & 7) << 2;
                cp_async16(sbase + B16_STGA + (uint32_t)((r * 32 + c4) * 4),
                           A + (long)(rowBase + r) * 1024 + k1 + c4);
                int rb = idx >> 5, cb = (idx & 31) << 2;
                cp_async16(sbase + B16_STGB + (uint32_t)((rb * 128 + cb) * 4),
                           B + (long)(k1 + rb) * ldb + boff + colBase + cb);
            }
            cp_async_commit();
        }

        #pragma unroll
        for (int s = 0; s < 2; s++) {
            const int kb = s * 16;
            uint32_t ah0[4], al0[4], ah1[4], al1[4];
            #pragma unroll
            for (int i = 0; i < 4; i++) {
                int rr = m0 + row_a + ((i & 1) << 3);
                int kk = kb + 2 * colc + ((i >> 1) << 3);
                ah0[i] = *(const uint32_t*)&Ahi[rr * 40 + kk];
                al0[i] = *(const uint32_t*)&Alo[rr * 40 + kk];
                ah1[i] = *(const uint32_t*)&Ahi[(rr + 16) * 40 + kk];
                al1[i] = *(const uint32_t*)&Alo[(rr + 16) * 40 + kk];
            }
            #pragma unroll
            for (int j2 = 0; j2 < 4; j2++) {
                uint32_t off =
                    (uint32_t)(((kb + lm_k) * 136 + n0w + j2 * 16 + lm_d) * 2);
                uint32_t h0, h1, h2, h3, l0, l1, l2, l3;
                ldmx4t(h0, h1, h2, h3, bhi_base + off);
                ldmx4t(l0, l1, l2, l3, blo_base + off);
                int jn = j2 * 2;
                mma_bf16(acc[0][jn], ah0, h0, h1);
                mma_bf16(acc[0][jn], al0, h0, h1);
                mma_bf16(acc[0][jn], ah0, l0, l1);
                mma_bf16(acc[1][jn], ah1, h0, h1);
                mma_bf16(acc[1][jn], al1, h0, h1);
                mma_bf16(acc[1][jn], ah1, l0, l1);
                mma_bf16(acc[0][jn+1], ah0, h2, h3);
                mma_bf16(acc[0][jn+1], al0, h2, h3);
                mma_bf16(acc[0][jn+1], ah0, l2, l3);
                mma_bf16(acc[1][jn+1], ah1, h2, h3);
                mma_bf16(acc[1][jn+1], al1, h2, h3);
                mma_bf16(acc[1][jn+1], ah1, l2, l3);
            }
        }
        __syncthreads();
    }

    #pragma unroll
    for (int j = 0; j < 8; j++) {
        int col = colBase + n0w + j * 8 + 2 * colc;
        float bx = bias ? bias[col] : 0.f;
        float by = bias ? bias[col + 1] : 0.f;
        #pragma unroll
        for (int m = 0; m < 2; m++) {
            int row = rowBase + m0 + m * 16 + row_a;
            *(float2*)(C + (long)row * 1024 + col) =
                make_float2(acc[m][j][0] + bx, acc[m][j][1] + by);
            *(float2*)(C + (long)(row + 8) * 1024 + col) =
                make_float2(acc[m][j][2] + bx, acc[m][j][3] + by);
        }
    }
}

// ===========================================================================
// Pre-convert K,V once: fp32 [b,key,h*64+d] -> per-head [b][h][key][64]
//   K: fp16 hi + fp16 (lo*2048)  (scaled lo avoids fp16 denormals)
//   V: bf16 hi/lo (identical rounding to the old in-flash path)
// ===========================================================================
__global__ void convert_kv(const float* __restrict__ k,
                           const float* __restrict__ v,
                           __half* __restrict__ kh, __half* __restrict__ kl,
                           __nv_bfloat16* __restrict__ vh,
                           __nv_bfloat16* __restrict__ vl)
{
    int i4 = blockIdx.x * blockDim.x + threadIdx.x;   // 4-elem chunks
    if (i4 >= ROWS * DMODEL / 4) return;
    int e = i4 * 4;
    int r = e >> 10;            // global row
    int c = e & 1023;
    int b = r >> 11, key = r & 2047;
    int h = c >> 6,  d = c & 63;
    long o = (((long)(b * HEADS + h) * SEQ + key) << 6) + d;

    float4 kf = *(const float4*)(k + e);
    float4 vf = *(const float4*)(v + e);
    float ka[4] = {kf.x, kf.y, kf.z, kf.w};
    uint32_t khp[2], klp[2];
    #pragma unroll
    for (int p = 0; p < 2; p++) {
        __half h0 = __float2half_rn(ka[2*p]);
        __half h1 = __float2half_rn(ka[2*p+1]);
        khp[p] = ((uint32_t)__half_as_ushort(h1) << 16) | __half_as_ushort(h0);
        __half l0 = __float2half_rn((ka[2*p]   - __half2float(h0)) * 2048.f);
        __half l1 = __float2half_rn((ka[2*p+1] - __half2float(h1)) * 2048.f);
        klp[p] = ((uint32_t)__half_as_ushort(l1) << 16) | __half_as_ushort(l0);
    }
    *(uint2*)(kh + o) = make_uint2(khp[0], khp[1]);
    *(uint2*)(kl + o) = make_uint2(klp[0], klp[1]);

    uint2 vhp, vlp;
    vhp.x = pack_bf16x2(vf.x, vf.y);
    vhp.y = pack_bf16x2(vf.z, vf.w);
    vlp.x = pack_bf16x2(vf.x - __uint_as_float(vhp.x << 16),
                        vf.y - __uint_as_float(vhp.x & 0xFFFF0000u));
    vlp.y = pack_bf16x2(vf.z - __uint_as_float(vhp.y << 16),
                        vf.w - __uint_as_float(vhp.y & 0xFFFF0000u));
    *(uint2*)(vh + o) = vhp;
    *(uint2*)(vl + o) = vlp;
}

// ===========================================================================
// Flash attention v4: fp16 3-term QK (scaled-lo, dual accumulator),
// bf16 3-term PV, pre-converted operands, double-buffered cp.async,
// all smem reads via ldmatrix. Mask = reference fp32 rounding.
// ===========================================================================
#define FB_KHI  0
#define FB_KLO  9216
#define FB_VHI  18432
#define FB_VLO  27648
#define FB_SIZE 36864
#define FLASH_SMEM (2*FB_SIZE)    // 73728

__global__ __launch_bounds__(128, 2)
void flash_mma(const float* __restrict__ Q,
               const __half* __restrict__ KH, const __half* __restrict__ KL,
               const __nv_bfloat16* __restrict__ VH,
               const __nv_bfloat16* __restrict__ VL,
               const int* __restrict__ mask, float* __restrict__ O)
{
    extern __shared__ char smem[];
    const uint32_t sbase = (uint32_t)__cvta_generic_to_shared(smem);

    const int b  = blockIdx.z;
    const int h  = blockIdx.y;
    const int n0 = blockIdx.x * 64;

    const int tid   = threadIdx.x;
    const int wid   = tid >> 5;
    const int lane  = tid & 31;
    const int r0    = wid * 16;
    const int row_a = lane >> 2;
    const int colc  = lane & 3;

    const long baseQ  = (long)b * SEQ * DMODEL + (long)h * DHEAD;
    const long baseKV = ((long)(b * HEADS + h) * SEQ) << 6;   // [key][64]

    // ldmatrix lane->addr mappings
    const int lmn_key = ((lane >> 4) << 3) + (lane & 7);  // K non-trans x4
    const int lmn_d   = ((lane >> 3) & 1) << 3;
    const int lmt_k   = lane & 15;                         // V trans x4
    const int lmt_d   = (lane >> 4) * 8;

    // staging coords: 512 16B-chunks per array, 4 per thread
    const int sg_r = tid >> 3;            // +16 per p? (128 thr, idx>>3)
    const int sg_c = (tid & 7) << 3;      // halves

    // ---- prefetch tile 0 into buffer 0 ----
    #pragma unroll
    for (int p = 0; p < 4; p++) {
        int idx = tid + p * 128;
        int r = idx >> 3, c8 = (idx & 7) << 3;
        uint32_t doff = (uint32_t)((r * 72 + c8) << 1);
        long go = baseKV + (r << 6) + c8;
        cp_async16(sbase + FB_KHI + doff, KH + go);
        cp_async16(sbase + FB_KLO + doff, KL + go);
        cp_async16(sbase + FB_VHI + doff, VH + go);
        cp_async16(sbase + FB_VLO + doff, VL + go);
    }
    cp_async_commit();

    // ---- Q fragments: fp16 hi + fp16 lo*2048, packed half2, registers ----
    uint32_t qh[4][4], qls[4][4];
    #pragma unroll
    for (int s = 0; s < 4; s++) {
        #pragma unroll
        for (int i = 0; i < 4; i++) {
            int rr = n0 + r0 + row_a + ((i & 1) << 3);
            int kb = (s << 4) + 2 * colc + ((i >> 1) << 3);
            float q0 = Q[baseQ + (long)rr * DMODEL + kb];
            float q1 = Q[baseQ + (long)rr * DMODEL + kb + 1];
            __half h0 = __float2half_rn(q0);
            __half h1 = __float2half_rn(q1);
            qh[s][i] = ((uint32_t)__half_as_ushort(h1) << 16) | __half_as_ushort(h0);
            qls[s][i] = pack_f16x2((q0 - __half2float(h0)) * 2048.f,
                                   (q1 - __half2float(h1)) * 2048.f);
        }
    }

    const float pen0 = (1.0f - (float)mask[b*SEQ + n0 + r0 + row_a])     * MASK_NEG;
    const float pen1 = (1.0f - (float)mask[b*SEQ + n0 + r0 + row_a + 8]) * MASK_NEG;

    float Oacc[32];
    #pragma unroll
    for (int i = 0; i < 32; i++) Oacc[i] = 0.f;
    float mstat[2] = {-1e30f, -1e30f};
    float lstat[2] = {0.f, 0.f};

    for (int kt = 0; kt < SEQ / 64; kt++) {
        cp_async_wait0();
        __syncthreads();
        const uint32_t buf = sbase + (uint32_t)((kt & 1) * FB_SIZE);

        // prefetch next tile into the other buffer (overlaps compute)
        if (kt + 1 < SEQ / 64) {
            const uint32_t nbuf = sbase + (uint32_t)(((kt + 1) & 1) * FB_SIZE);
            const long gb = baseKV + ((long)(kt + 1) << 12);   // +64 keys *64
            #pragma unroll
            for (int p = 0; p < 4; p++) {
                int idx = tid + p * 128;
                int r = idx >> 3, c8 = (idx & 7) << 3;
                uint32_t doff = (uint32_t)((r * 72 + c8) << 1);
                long go = gb + (r << 6) + c8;
                cp_async16(nbuf + FB_KHI + doff, KH + go);
                cp_async16(nbuf + FB_KLO + doff, KL + go);
                cp_async16(nbuf + FB_VHI + doff, VH + go);
                cp_async16(nbuf + FB_VLO + doff, VL + go);
            }
            cp_async_commit();
        }

        // ---- S = Q K^T : fp16, S1 = hi*hi ; S2 = lo_s*hi + hi*lo_s ----
        float S1[32], S2[32];
        #pragma unroll
        for (int i = 0; i < 32; i++) { S1[i] = 0.f; S2[i] = 0.f; }

        const uint32_t khi_b = buf + FB_KHI;
        const uint32_t klo_b = buf + FB_KLO;
        #pragma unroll
        for (int s = 0; s < 4; s++) {
            #pragma unroll
            for (int jk = 0; jk < 4; jk++) {   // 16 keys per x4
                uint32_t off = (uint32_t)((((jk << 4) + lmn_key) * 72
                                           + (s << 4) + lmn_d) << 1);
                uint32_t h0, h1, h2, h3, l0, l1, l2, l3;
                ldmx4(h0, h1, h2, h3, khi_b + off);
                ldmx4(l0, l1, l2, l3, klo_b + off);
                int j0 = jk * 2;
                mma_fp16(&S1[j0*4], qh[s],  h0, h1);
                mma_fp16(&S2[j0*4], qls[s], h0, h1);
                mma_fp16(&S2[j0*4], qh[s],  l0, l1);
                mma_fp16(&S1[(j0+1)*4], qh[s],  h2, h3);
                mma_fp16(&S2[(j0+1)*4], qls[s], h2, h3);
                mma_fp16(&S2[(j0+1)*4], qh[s],  l2, l3);
            }
        }

        float S[32];
        #pragma unroll
        for (int i = 0; i < 32; i++)
            S[i] = fmaf(S2[i], 4.8828125e-4f, S1[i]);   // + S2/2048

        // ---- scale + mask (reference fp32 rounding) + online softmax ----
        #pragma unroll
        for (int t = 0; t < 2; t++) {
            float pent = t ? pen1 : pen0;
            float mloc = -1e30f;
            #pragma unroll
            for (int j = 0; j < 8; j++) {
                float v0 = S[j*4 + 2*t]     * ATT_SCALE - pent;
                float v1 = S[j*4 + 2*t + 1] * ATT_SCALE - pent;
                S[j*4 + 2*t]     = v0;
                S[j*4 + 2*t + 1] = v1;
                mloc = fmaxf(mloc, fmaxf(v0, v1));
            }
            mloc = fmaxf(mloc, __shfl_xor_sync(0xffffffffu, mloc, 1));
            mloc = fmaxf(mloc, __shfl_xor_sync(0xffffffffu, mloc, 2));
            float mnew  = fmaxf(mstat[t], mloc);
            float alpha = __expf(mstat[t] - mnew);
            float lloc = 0.f;
            #pragma unroll
            for (int j = 0; j < 8; j++) {
                float p0 = __expf(S[j*4 + 2*t]     - mnew);
                float p1 = __expf(S[j*4 + 2*t + 1] - mnew);
                S[j*4 + 2*t]     = p0;
                S[j*4 + 2*t + 1] = p1;
                lloc += p0 + p1;
            }
            lloc += __shfl_xor_sync(0xffffffffu, lloc, 1);
            lloc += __shfl_xor_sync(0xffffffffu, lloc, 2);
            lstat[t] = lstat[t] * alpha + lloc;
            mstat[t] = mnew;
            #pragma unroll
            for (int j = 0; j < 8; j++) {
                Oacc[j*4 + 2*t]     *= alpha;
                Oacc[j*4 + 2*t + 1] *= alpha;
            }
        }

        // ---- O += P V (bf16 3-term); V via ldmatrix.x4.trans ----
        const uint32_t vhi_b = buf + FB_VHI;
        const uint32_t vlo_b = buf + FB_VLO;
        #pragma unroll
        for (int t2 = 0; t2 < 4; t2++) {
            uint32_t ah[4], al[4];
            #pragma unroll
            for (int i = 0; i < 4; i++) {
                int jt  = 2*t2 + (i >> 1);
                int off = (i & 1) * 2;
                float p0 = S[jt*4 + off];
                float p1 = S[jt*4 + off + 1];
                uint32_t hh = pack_bf16x2(p0, p1);
                ah[i] = hh;
                al[i] = pack_bf16x2(p0 - __uint_as_float(hh << 16),
                                    p1 - __uint_as_float(hh & 0xFFFF0000u));
            }
            const uint32_t row_off =
                (uint32_t)(((t2 * 16 + lmt_k) * 72 + lmt_d) * 2);
            #pragma unroll
            for (int j2 = 0; j2 < 4; j2++) {
                uint32_t off = row_off + (uint32_t)(j2 * 16 * 2);
                uint32_t h0, h1, h2, h3, l0, l1, l2, l3;
                ldmx4t(h0, h1, h2, h3, vhi_b + off);
                ldmx4t(l0, l1, l2, l3, vlo_b + off);
                mma_bf16(&Oacc[(2*j2)*4], ah, h0, h1);
                mma_bf16(&Oacc[(2*j2)*4], al, h0, h1);
                mma_bf16(&Oacc[(2*j2)*4], ah, l0, l1);
                mma_bf16(&Oacc[(2*j2+1)*4], ah, h2, h3);
                mma_bf16(&Oacc[(2*j2+1)*4], al, h2, h3);
                mma_bf16(&Oacc[(2*j2+1)*4], ah, l2, l3);
            }
        }
    }

    // ---- normalize + store ----
    float inv0 = 1.f / lstat[0];
    float inv1 = 1.f / lstat[1];
    int rowg = n0 + r0 + row_a;
    #pragma unroll
    for (int j = 0; j < 8; j++) {
        float2 v0 = make_float2(Oacc[j*4 + 0] * inv0, Oacc[j*4 + 1] * inv0);
        float2 v1 = make_float2(Oacc[j*4 + 2] * inv1, Oacc[j*4 + 3] * inv1);
        *(float2*)(O + baseQ + (long)rowg       * DMODEL + j*8 + 2*colc) = v0;
        *(float2*)(O + baseQ + (long)(rowg + 8) * DMODEL + j*8 + 2*colc) = v1;
    }
}

// ---------------------------------------------------------------------------
// Launch
// ---------------------------------------------------------------------------
extern "C" void kernel_launch(void* const* d_in, const int* in_sizes, int n_in,
                              void* d_out, int out_size)
{
    const float* x       = (const float*)d_in[0];
    const float* context = (const float*)d_in[1];
    const int*   mask    = (const int*)d_in[2];
    const float* Wq      = (const float*)d_in[3];
    const float* Wkv     = (const float*)d_in[4];
    const float* Wout    = (const float*)d_in[5];
    const float* bout    = (const float*)d_in[6];
    float* out = (float*)d_out;

    float *q, *k, *v, *o;
    cudaGetSymbolAddress((void**)&q, g_q);
    cudaGetSymbolAddress((void**)&k, g_k);
    cudaGetSymbolAddress((void**)&v, g_v);
    cudaGetSymbolAddress((void**)&o, g_o);
    __half *kh, *kl;
    __nv_bfloat16 *vh, *vl;
    cudaGetSymbolAddress((void**)&kh, g_kh);
    cudaGetSymbolAddress((void**)&kl, g_kl);
    cudaGetSymbolAddress((void**)&vh, g_vh);
    cudaGetSymbolAddress((void**)&vl, g_vl);

    cudaFuncSetAttribute(flash_mma,
                         cudaFuncAttributeMaxDynamicSharedMemorySize, FLASH_SMEM);
    cudaFuncSetAttribute(gemm_tf32,
                         cudaFuncAttributeMaxDynamicSharedMemorySize, T32_SMEM);
    cudaFuncSetAttribute(gemm_bf16,
                         cudaFuncAttributeMaxDynamicSharedMemorySize, B16_SMEM);

    dim3 gg(1024 / 128, 4096 / 128);

    // projections
    gemm_tf32<<<gg, 256, T32_SMEM>>>(x, Wq, q, INNER, 0, nullptr);
    gemm_tf32<<<gg, 256, T32_SMEM>>>(context, Wkv, k, 2 * INNER, 0, nullptr);
    gemm_bf16<<<gg, 256, B16_SMEM>>>(context, Wkv, v, 2 * INNER, INNER, nullptr);

    // one-time K/V conversion to per-head fp16/bf16 hi-lo
    convert_kv<<<ROWS * DMODEL / 4 / 256, 256>>>(k, v, kh, kl, vh, vl);

    // attention
    dim3 grid_attn(SEQ / 64, HEADS, BATCH);
    flash_mma<<<grid_attn, 128, FLASH_SMEM>>>(q, kh, kl, vh, vl, mask, o);

    // output projection
    gemm_bf16<<<gg, 256, B16_SMEM>>>(o, Wout, out, INNER, 0, bout);
}

// round 12
// speedup vs baseline: 2.7597x; 1.1247x over previous
#include <cuda_runtime.h>
#include <cuda_bf16.h>
#include <cuda_fp16.h>
#include <math.h>
#include <stdint.h>

// Problem constants
#define BATCH   2
#define SEQ     2048
#define DMODEL  1024
#define HEADS   16
#define DHEAD   64
#define INNER   (HEADS*DHEAD)      // 1024
#define ROWS    (BATCH*SEQ)        // 4096
#define ATT_SCALE 0.125f
#define MASK_NEG 1000000.0f

// ---------------------------------------------------------------------------
// Scratch (allocation-free rule: static __device__ globals)
// ---------------------------------------------------------------------------
__device__ float g_q[ROWS*INNER];
__device__ float g_k[ROWS*INNER];
__device__ float g_v[ROWS*INNER];
// flash K/V operands, per-head layout [b][h][key][64]
__device__ __half        g_kh[ROWS*INNER];
__device__ __half        g_kl[ROWS*INNER];   // lo * 2048
__device__ __nv_bfloat16 g_vh[ROWS*INNER];
__device__ __nv_bfloat16 g_vl[ROWS*INNER];
// pre-split GEMM operands
__device__ float g_xh[ROWS*DMODEL],  g_xl[ROWS*DMODEL];      // x  tf32
__device__ float g_cth[ROWS*DMODEL], g_ctl[ROWS*DMODEL];     // context tf32
__device__ float g_wqh[DMODEL*INNER], g_wql[DMODEL*INNER];   // Wq tf32
__device__ float g_wkh[DMODEL*INNER], g_wkl[DMODEL*INNER];   // Wkv[:, :1024] tf32
__device__ __nv_bfloat16 g_ctbh[ROWS*DMODEL], g_ctbl[ROWS*DMODEL];   // context bf16
__device__ __nv_bfloat16 g_wvbh[DMODEL*INNER], g_wvbl[DMODEL*INNER]; // Wkv[:,1024:] bf16
__device__ __nv_bfloat16 g_wobh[INNER*DMODEL], g_wobl[INNER*DMODEL]; // Wout bf16
__device__ __nv_bfloat16 g_obh[ROWS*INNER], g_obl[ROWS*INNER];       // flash O bf16

// ---------------------------------------------------------------------------
// mma.sync / ldmatrix / cp.async helpers (compute_103-compatible; NO tcgen05)
// ---------------------------------------------------------------------------
__device__ __forceinline__ void mma_tf32(float* d, const uint32_t* a,
                                         uint32_t b0, uint32_t b1)
{
    asm volatile(
        "mma.sync.aligned.m16n8k8.row.col.f32.tf32.tf32.f32 "
        "{%0,%1,%2,%3}, {%4,%5,%6,%7}, {%8,%9}, {%0,%1,%2,%3};"
        : "+f"(d[0]), "+f"(d[1]), "+f"(d[2]), "+f"(d[3])
        : "r"(a[0]), "r"(a[1]), "r"(a[2]), "r"(a[3]), "r"(b0), "r"(b1));
}

__device__ __forceinline__ void mma_bf16(float* d, const uint32_t* a,
                                         uint32_t b0, uint32_t b1)
{
    asm volatile(
        "mma.sync.aligned.m16n8k16.row.col.f32.bf16.bf16.f32 "
        "{%0,%1,%2,%3}, {%4,%5,%6,%7}, {%8,%9}, {%0,%1,%2,%3};"
        : "+f"(d[0]), "+f"(d[1]), "+f"(d[2]), "+f"(d[3])
        : "r"(a[0]), "r"(a[1]), "r"(a[2]), "r"(a[3]), "r"(b0), "r"(b1));
}

__device__ __forceinline__ void mma_fp16(float* d, const uint32_t* a,
                                         uint32_t b0, uint32_t b1)
{
    asm volatile(
        "mma.sync.aligned.m16n8k16.row.col.f32.f16.f16.f32 "
        "{%0,%1,%2,%3}, {%4,%5,%6,%7}, {%8,%9}, {%0,%1,%2,%3};"
        : "+f"(d[0]), "+f"(d[1]), "+f"(d[2]), "+f"(d[3])
        : "r"(a[0]), "r"(a[1]), "r"(a[2]), "r"(a[3]), "r"(b0), "r"(b1));
}

__device__ __forceinline__ uint32_t f2tf32(float x) {
    uint32_t r; asm("cvt.rna.tf32.f32 %0, %1;" : "=r"(r) : "f"(x)); return r;
}

__device__ __forceinline__ uint32_t pack_bf16x2(float lo_val, float hi_val) {
    uint32_t r;
    asm("cvt.rn.bf16x2.f32 %0, %1, %2;" : "=r"(r) : "f"(hi_val), "f"(lo_val));
    return r;
}

__device__ __forceinline__ uint32_t pack_f16x2(float lo_val, float hi_val) {
    __half h0 = __float2half_rn(lo_val);
    __half h1 = __float2half_rn(hi_val);
    return ((uint32_t)__half_as_ushort(h1) << 16) | __half_as_ushort(h0);
}

__device__ __forceinline__ void ldmx4t(uint32_t& r0, uint32_t& r1,
                                       uint32_t& r2, uint32_t& r3, uint32_t addr)
{
    asm volatile(
        "ldmatrix.sync.aligned.m8n8.x4.trans.shared.b16 {%0,%1,%2,%3}, [%4];"
        : "=r"(r0), "=r"(r1), "=r"(r2), "=r"(r3) : "r"(addr));
}
__device__ __forceinline__ void ldmx4(uint32_t& r0, uint32_t& r1,
                                      uint32_t& r2, uint32_t& r3, uint32_t addr)
{
    asm volatile(
        "ldmatrix.sync.aligned.m8n8.x4.shared.b16 {%0,%1,%2,%3}, [%4];"
        : "=r"(r0), "=r"(r1), "=r"(r2), "=r"(r3) : "r"(addr));
}

__device__ __forceinline__ void cp_async16(uint32_t saddr, const void* gptr) {
    asm volatile("cp.async.cg.shared.global [%0], [%1], 16;"
                 :: "r"(saddr), "l"(gptr));
}
__device__ __forceinline__ void cp_async_commit() {
    asm volatile("cp.async.commit_group;");
}
__device__ __forceinline__ void cp_async_wait0() {
    asm volatile("cp.async.wait_group 0;");
}
__device__ __forceinline__ void cp_async_wait1() {
    asm volatile("cp.async.wait_group 1;");
}

// ===========================================================================
// One-time operand split kernels (rounding identical to the old in-GEMM path)
// ===========================================================================
__global__ void split_t32(const float* __restrict__ src,
                          float* __restrict__ hi, float* __restrict__ lo, int n4)
{
    int i = blockIdx.x * blockDim.x + threadIdx.x;
    if (i >= n4) return;
    float4 x = ((const float4*)src)[i];
    float4 h, l;
    uint32_t b;
    b = f2tf32(x.x); h.x = __uint_as_float(b); l.x = __uint_as_float(f2tf32(x.x - h.x));
    b = f2tf32(x.y); h.y = __uint_as_float(b); l.y = __uint_as_float(f2tf32(x.y - h.y));
    b = f2tf32(x.z); h.z = __uint_as_float(b); l.z = __uint_as_float(f2tf32(x.z - h.z));
    b = f2tf32(x.w); h.w = __uint_as_float(b); l.w = __uint_as_float(f2tf32(x.w - h.w));
    ((float4*)hi)[i] = h;
    ((float4*)lo)[i] = l;
}

// tf32 split of a 1024-wide column slice of a [1024][cols_src] matrix
__global__ void split_t32_slice(const float* __restrict__ src,
                                float* __restrict__ hi, float* __restrict__ lo,
                                int cols_src, int col0)
{
    int i = blockIdx.x * blockDim.x + threadIdx.x;   // float4 within [1024][1024]
    if (i >= DMODEL * INNER / 4) return;
    int e = i * 4;
    int r = e >> 10, c = e & 1023;
    float4 x = *(const float4*)(src + (long)r * cols_src + col0 + c);
    float4 h, l;
    uint32_t b;
    b = f2tf32(x.x); h.x = __uint_as_float(b); l.x = __uint_as_float(f2tf32(x.x - h.x));
    b = f2tf32(x.y); h.y = __uint_as_float(b); l.y = __uint_as_float(f2tf32(x.y - h.y));
    b = f2tf32(x.z); h.z = __uint_as_float(b); l.z = __uint_as_float(f2tf32(x.z - h.z));
    b = f2tf32(x.w); h.w = __uint_as_float(b); l.w = __uint_as_float(f2tf32(x.w - h.w));
    ((float4*)hi)[i] = h;
    ((float4*)lo)[i] = l;
}

__global__ void split_b16(const float* __restrict__ src,
                          __nv_bfloat16* __restrict__ hi,
                          __nv_bfloat16* __restrict__ lo, int n4)
{
    int i = blockIdx.x * blockDim.x + threadIdx.x;
    if (i >= n4) return;
    float4 x = ((const float4*)src)[i];
    uint2 h, l;
    h.x = pack_bf16x2(x.x, x.y);
    h.y = pack_bf16x2(x.z, x.w);
    l.x = pack_bf16x2(x.x - __uint_as_float(h.x << 16),
                      x.y - __uint_as_float(h.x & 0xFFFF0000u));
    l.y = pack_bf16x2(x.z - __uint_as_float(h.y << 16),
                      x.w - __uint_as_float(h.y & 0xFFFF0000u));
    ((uint2*)hi)[i] = h;
    ((uint2*)lo)[i] = l;
}

__global__ void split_b16_slice(const float* __restrict__ src,
                                __nv_bfloat16* __restrict__ hi,
                                __nv_bfloat16* __restrict__ lo,
                                int cols_src, int col0)
{
    int i = blockIdx.x * blockDim.x + threadIdx.x;
    if (i >= DMODEL * INNER / 4) return;
    int e = i * 4;
    int r = e >> 10, c = e & 1023;
    float4 x = *(const float4*)(src + (long)r * cols_src + col0 + c);
    uint2 h, l;
    h.x = pack_bf16x2(x.x, x.y);
    h.y = pack_bf16x2(x.z, x.w);
    l.x = pack_bf16x2(x.x - __uint_as_float(h.x << 16),
                      x.y - __uint_as_float(h.x & 0xFFFF0000u));
    l.y = pack_bf16x2(x.z - __uint_as_float(h.y << 16),
                      x.w - __uint_as_float(h.y & 0xFFFF0000u));
    ((uint2*)hi)[i] = h;
    ((uint2*)lo)[i] = l;
}

// ===========================================================================
// GEMM tf32 3-term, PRE-SPLIT operands, 2-deep cp.async pipeline.
// C[4096 x 1024] = A * B ; A hi/lo [4096][1024] fp32(tf32-valued),
// B hi/lo [1024][1024]. Tile 128x128, chunk 32, 256 thr.
// ===========================================================================
#define P32_AHI  0
#define P32_ALO  18432          // 128*36*4
#define P32_BHI  36864
#define P32_BLO  54272          // + 32*136*4
#define P32_STAGE 71680
#define P32_SMEM (2*P32_STAGE)  // 143360

__global__ __launch_bounds__(256, 1)
void gemm_tf32_ps(const float* __restrict__ Ah, const float* __restrict__ Al,
                  const float* __restrict__ Bh, const float* __restrict__ Bl,
                  float* __restrict__ C)
{
    extern __shared__ char smem[];
    const uint32_t sbase = (uint32_t)__cvta_generic_to_shared(smem);

    const int tid = threadIdx.x;
    const int wid = tid >> 5;
    const int lane = tid & 31;
    const int row_a = lane >> 2;
    const int colc  = lane & 3;
    const int m0  = (wid >> 1) * 32;
    const int n0w = (wid & 1) * 64;
    const int rowBase = blockIdx.y * 128;
    const int colBase = blockIdx.x * 128;

    // A: 1024 16B-chunks per (hi|lo); B: 1024 per (hi|lo); 16 cp per thread
    const int a_r = tid >> 1;              // with p-loop below
    auto load_stage = [&](int stg, int kc) {
        const uint32_t sb = sbase + (uint32_t)(stg * P32_STAGE);
        const long ka = (long)kc * 32;
        #pragma unroll
        for (int p = 0; p < 4; p++) {
            int idx = tid + p * 256;
            int r = idx >> 3, c = (idx & 7) << 2;       // A: 128 rows x 8 chunks
            long ga = (long)(rowBase + r) * 1024 + ka + c;
            uint32_t da = (uint32_t)(r * 144 + c * 4);
            cp_async16(sb + P32_AHI + da, Ah + ga);
            cp_async16(sb + P32_ALO + da, Al + ga);
            int rb = idx >> 5, cb = (idx & 31) << 2;    // B: 32 rows x 32 chunks
            long gb = (ka + rb) * 1024 + colBase + cb;
            uint32_t db = (uint32_t)(rb * 544 + cb * 4);
            cp_async16(sb + P32_BHI + db, Bh + gb);
            cp_async16(sb + P32_BLO + db, Bl + gb);
        }
    };
    (void)a_r;

    load_stage(0, 0);
    cp_async_commit();

    float acc[2][8][4];
    #pragma unroll
    for (int m = 0; m < 2; m++)
        #pragma unroll
        for (int j = 0; j < 8; j++)
            #pragma unroll
            for (int c = 0; c < 4; c++) acc[m][j][c] = 0.f;

    for (int kc = 0; kc < 32; kc++) {
        if (kc + 1 < 32) {
            load_stage((kc + 1) & 1, kc + 1);
            cp_async_commit();
            cp_async_wait1();
        } else {
            cp_async_wait0();
        }
        __syncthreads();

        const char* buf = smem + (kc & 1) * P32_STAGE;
        const float* Ahi = (const float*)(buf + P32_AHI);
        const float* Alo = (const float*)(buf + P32_ALO);
        const float* Bhi = (const float*)(buf + P32_BHI);
        const float* Blo = (const float*)(buf + P32_BLO);

        #pragma unroll
        for (int s = 0; s < 4; s++) {
            const int kb = s * 8;
            uint32_t ah0[4], al0[4], ah1[4], al1[4];
            #pragma unroll
            for (int i = 0; i < 4; i++) {
                int rr = m0 + row_a + ((i & 1) << 3);
                int kk = kb + colc + ((i >> 1) << 2);
                ah0[i] = __float_as_uint(Ahi[rr * 36 + kk]);
                al0[i] = __float_as_uint(Alo[rr * 36 + kk]);
                ah1[i] = __float_as_uint(Ahi[(rr + 16) * 36 + kk]);
                al1[i] = __float_as_uint(Alo[(rr + 16) * 36 + kk]);
            }
            #pragma unroll
            for (int j = 0; j < 8; j++) {
                int nc = n0w + j * 8 + row_a;
                int i0 = (kb + colc) * 136 + nc;
                int i1 = (kb + colc + 4) * 136 + nc;
                uint32_t bh0 = __float_as_uint(Bhi[i0]);
                uint32_t bh1 = __float_as_uint(Bhi[i1]);
                uint32_t bl0 = __float_as_uint(Blo[i0]);
                uint32_t bl1 = __float_as_uint(Blo[i1]);
                mma_tf32(acc[0][j], ah0, bh0, bh1);
                mma_tf32(acc[0][j], al0, bh0, bh1);
                mma_tf32(acc[0][j], ah0, bl0, bl1);
                mma_tf32(acc[1][j], ah1, bh0, bh1);
                mma_tf32(acc[1][j], al1, bh0, bh1);
                mma_tf32(acc[1][j], ah1, bl0, bl1);
            }
        }
        __syncthreads();
    }

    #pragma unroll
    for (int j = 0; j < 8; j++) {
        int col = colBase + n0w + j * 8 + 2 * colc;
        #pragma unroll
        for (int m = 0; m < 2; m++) {
            int row = rowBase + m0 + m * 16 + row_a;
            *(float2*)(C + (long)row * 1024 + col) =
                make_float2(acc[m][j][0], acc[m][j][1]);
            *(float2*)(C + (long)(row + 8) * 1024 + col) =
                make_float2(acc[m][j][2], acc[m][j][3]);
        }
    }
}

// ===========================================================================
// GEMM bf16 3-term, PRE-SPLIT operands, 2-deep pipeline.
// A hi/lo [4096][1024] bf16, B hi/lo [1024][1024] bf16.
// ===========================================================================
#define P16_AHI  0
#define P16_ALO  10240          // 128*40*2
#define P16_BHI  20480
#define P16_BLO  29184          // + 32*136*2
#define P16_STAGE 37888
#define P16_SMEM (2*P16_STAGE)  // 75776

__global__ __launch_bounds__(256, 1)
void gemm_bf16_ps(const __nv_bfloat16* __restrict__ Ah,
                  const __nv_bfloat16* __restrict__ Al,
                  const __nv_bfloat16* __restrict__ Bh,
                  const __nv_bfloat16* __restrict__ Bl,
                  float* __restrict__ C, const float* __restrict__ bias)
{
    extern __shared__ char smem[];
    const uint32_t sbase = (uint32_t)__cvta_generic_to_shared(smem);

    const int tid = threadIdx.x;
    const int wid = tid >> 5;
    const int lane = tid & 31;
    const int row_a = lane >> 2;
    const int colc  = lane & 3;
    const int lm_k = lane & 15;
    const int lm_d = (lane >> 4) * 8;
    const int m0  = (wid >> 1) * 32;
    const int n0w = (wid & 1) * 64;
    const int rowBase = blockIdx.y * 128;
    const int colBase = blockIdx.x * 128;

    auto load_stage = [&](int stg, int kc) {
        const uint32_t sb = sbase + (uint32_t)(stg * P16_STAGE);
        const long ka = (long)kc * 32;
        #pragma unroll
        for (int p = 0; p < 2; p++) {
            int idx = tid + p * 256;
            int r = idx >> 2, c = (idx & 3) << 3;        // A: 128 rows x 4 chunks
            long ga = (long)(rowBase + r) * 1024 + ka + c;
            uint32_t da = (uint32_t)(r * 80 + c * 2);
            cp_async16(sb + P16_AHI + da, Ah + ga);
            cp_async16(sb + P16_ALO + da, Al + ga);
            int rb = idx >> 4, cb = (idx & 15) << 3;     // B: 32 rows x 16 chunks
            long gb = (ka + rb) * 1024 + colBase + cb;
            uint32_t db = (uint32_t)(rb * 272 + cb * 2);
            cp_async16(sb + P16_BHI + db, Bh + gb);
            cp_async16(sb + P16_BLO + db, Bl + gb);
        }
    };

    load_stage(0, 0);
    cp_async_commit();

    float acc[2][8][4];
    #pragma unroll
    for (int m = 0; m < 2; m++)
        #pragma unroll
        for (int j = 0; j < 8; j++)
            #pragma unroll
            for (int c = 0; c < 4; c++) acc[m][j][c] = 0.f;

    for (int kc = 0; kc < 32; kc++) {
        if (kc + 1 < 32) {
            load_stage((kc + 1) & 1, kc + 1);
            cp_async_commit();
            cp_async_wait1();
        } else {
            cp_async_wait0();
        }
        __syncthreads();

        const char* buf = smem + (kc & 1) * P16_STAGE;
        const __nv_bfloat16* Ahi = (const __nv_bfloat16*)(buf + P16_AHI);
        const __nv_bfloat16* Alo = (const __nv_bfloat16*)(buf + P16_ALO);
        const uint32_t bhi_base = sbase + (uint32_t)((kc & 1) * P16_STAGE) + P16_BHI;
        const uint32_t blo_base = sbase + (uint32_t)((kc & 1) * P16_STAGE) + P16_BLO;

        #pragma unroll
        for (int s = 0; s < 2; s++) {
            const int kb = s * 16;
            uint32_t ah0[4], al0[4], ah1[4], al1[4];
            #pragma unroll
            for (int i = 0; i < 4; i++) {
                int rr = m0 + row_a + ((i & 1) << 3);
                int kk = kb + 2 * colc + ((i >> 1) << 3);
                ah0[i] = *(const uint32_t*)&Ahi[rr * 40 + kk];
                al0[i] = *(const uint32_t*)&Alo[rr * 40 + kk];
                ah1[i] = *(const uint32_t*)&Ahi[(rr + 16) * 40 + kk];
                al1[i] = *(const uint32_t*)&Alo[(rr + 16) * 40 + kk];
            }
            #pragma unroll
            for (int j2 = 0; j2 < 4; j2++) {
                uint32_t off =
                    (uint32_t)(((kb + lm_k) * 136 + n0w + j2 * 16 + lm_d) * 2);
                uint32_t h0, h1, h2, h3, l0, l1, l2, l3;
                ldmx4t(h0, h1, h2, h3, bhi_base + off);
                ldmx4t(l0, l1, l2, l3, blo_base + off);
                int jn = j2 * 2;
                mma_bf16(acc[0][jn], ah0, h0, h1);
                mma_bf16(acc[0][jn], al0, h0, h1);
                mma_bf16(acc[0][jn], ah0, l0, l1);
                mma_bf16(acc[1][jn], ah1, h0, h1);
                mma_bf16(acc[1][jn], al1, h0, h1);
                mma_bf16(acc[1][jn], ah1, l0, l1);
                mma_bf16(acc[0][jn+1], ah0, h2, h3);
                mma_bf16(acc[0][jn+1], al0, h2, h3);
                mma_bf16(acc[0][jn+1], ah0, l2, l3);
                mma_bf16(acc[1][jn+1], ah1, h2, h3);
                mma_bf16(acc[1][jn+1], al1, h2, h3);
                mma_bf16(acc[1][jn+1], ah1, l2, l3);
            }
        }
        __syncthreads();
    }

    #pragma unroll
    for (int j = 0; j < 8; j++) {
        int col = colBase + n0w + j * 8 + 2 * colc;
        float bx = bias ? bias[col] : 0.f;
        float by = bias ? bias[col + 1] : 0.f;
        #pragma unroll
        for (int m = 0; m < 2; m++) {
            int row = rowBase + m0 + m * 16 + row_a;
            *(float2*)(C + (long)row * 1024 + col) =
                make_float2(acc[m][j][0] + bx, acc[m][j][1] + by);
            *(float2*)(C + (long)(row + 8) * 1024 + col) =
                make_float2(acc[m][j][2] + bx, acc[m][j][3] + by);
        }
    }
}

// ===========================================================================
// Pre-convert K,V: fp32 [b,key,h*64+d] -> per-head [b][h][key][64]
// ===========================================================================
__global__ void convert_kv(const float* __restrict__ k,
                           const float* __restrict__ v,
                           __half* __restrict__ kh, __half* __restrict__ kl,
                           __nv_bfloat16* __restrict__ vh,
                           __nv_bfloat16* __restrict__ vl)
{
    int i4 = blockIdx.x * blockDim.x + threadIdx.x;
    if (i4 >= ROWS * DMODEL / 4) return;
    int e = i4 * 4;
    int r = e >> 10;
    int c = e & 1023;
    int b = r >> 11, key = r & 2047;
    int h = c >> 6,  d = c & 63;
    long o = (((long)(b * HEADS + h) * SEQ + key) << 6) + d;

    float4 kf = *(const float4*)(k + e);
    float4 vf = *(const float4*)(v + e);
    float ka[4] = {kf.x, kf.y, kf.z, kf.w};
    uint32_t khp[2], klp[2];
    #pragma unroll
    for (int p = 0; p < 2; p++) {
        __half h0 = __float2half_rn(ka[2*p]);
        __half h1 = __float2half_rn(ka[2*p+1]);
        khp[p] = ((uint32_t)__half_as_ushort(h1) << 16) | __half_as_ushort(h0);
        __half l0 = __float2half_rn((ka[2*p]   - __half2float(h0)) * 2048.f);
        __half l1 = __float2half_rn((ka[2*p+1] - __half2float(h1)) * 2048.f);
        klp[p] = ((uint32_t)__half_as_ushort(l1) << 16) | __half_as_ushort(l0);
    }
    *(uint2*)(kh + o) = make_uint2(khp[0], khp[1]);
    *(uint2*)(kl + o) = make_uint2(klp[0], klp[1]);

    uint2 vhp, vlp;
    vhp.x = pack_bf16x2(vf.x, vf.y);
    vhp.y = pack_bf16x2(vf.z, vf.w);
    vlp.x = pack_bf16x2(vf.x - __uint_as_float(vhp.x << 16),
                        vf.y - __uint_as_float(vhp.x & 0xFFFF0000u));
    vlp.y = pack_bf16x2(vf.z - __uint_as_float(vhp.y << 16),
                        vf.w - __uint_as_float(vhp.y & 0xFFFF0000u));
    *(uint2*)(vh + o) = vhp;
    *(uint2*)(vl + o) = vlp;
}

// ===========================================================================
// Flash attention v4 (R11, passed) — epilogue now writes O as bf16 hi/lo
// (same rounding the out-projection GEMM applied; bit-identical pipeline).
// ===========================================================================
#define FB_KHI  0
#define FB_KLO  9216
#define FB_VHI  18432
#define FB_VLO  27648
#define FB_SIZE 36864
#define FLASH_SMEM (2*FB_SIZE)

__global__ __launch_bounds__(128, 2)
void flash_mma(const float* __restrict__ Q,
               const __half* __restrict__ KH, const __half* __restrict__ KL,
               const __nv_bfloat16* __restrict__ VH,
               const __nv_bfloat16* __restrict__ VL,
               const int* __restrict__ mask,
               __nv_bfloat16* __restrict__ OBH,
               __nv_bfloat16* __restrict__ OBL)
{
    extern __shared__ char smem[];
    const uint32_t sbase = (uint32_t)__cvta_generic_to_shared(smem);

    const int b  = blockIdx.z;
    const int h  = blockIdx.y;
    const int n0 = blockIdx.x * 64;

    const int tid   = threadIdx.x;
    const int wid   = tid >> 5;
    const int lane  = tid & 31;
    const int r0    = wid * 16;
    const int row_a = lane >> 2;
    const int colc  = lane & 3;

    const long baseQ  = (long)b * SEQ * DMODEL + (long)h * DHEAD;
    const long baseKV = ((long)(b * HEADS + h) * SEQ) << 6;

    const int lmn_key = ((lane >> 4) << 3) + (lane & 7);
    const int lmn_d   = ((lane >> 3) & 1) << 3;
    const int lmt_k   = lane & 15;
    const int lmt_d   = (lane >> 4) * 8;

    #pragma unroll
    for (int p = 0; p < 4; p++) {
        int idx = tid + p * 128;
        int r = idx >> 3, c8 = (idx & 7) << 3;
        uint32_t doff = (uint32_t)((r * 72 + c8) << 1);
        long go = baseKV + (r << 6) + c8;
        cp_async16(sbase + FB_KHI + doff, KH + go);
        cp_async16(sbase + FB_KLO + doff, KL + go);
        cp_async16(sbase + FB_VHI + doff, VH + go);
        cp_async16(sbase + FB_VLO + doff, VL + go);
    }
    cp_async_commit();

    uint32_t qh[4][4], qls[4][4];
    #pragma unroll
    for (int s = 0; s < 4; s++) {
        #pragma unroll
        for (int i = 0; i < 4; i++) {
            int rr = n0 + r0 + row_a + ((i & 1) << 3);
            int kb = (s << 4) + 2 * colc + ((i >> 1) << 3);
            float q0 = Q[baseQ + (long)rr * DMODEL + kb];
            float q1 = Q[baseQ + (long)rr * DMODEL + kb + 1];
            __half h0 = __float2half_rn(q0);
            __half h1 = __float2half_rn(q1);
            qh[s][i] = ((uint32_t)__half_as_ushort(h1) << 16) | __half_as_ushort(h0);
            qls[s][i] = pack_f16x2((q0 - __half2float(h0)) * 2048.f,
                                   (q1 - __half2float(h1)) * 2048.f);
        }
    }

    const float pen0 = (1.0f - (float)mask[b*SEQ + n0 + r0 + row_a])     * MASK_NEG;
    const float pen1 = (1.0f - (float)mask[b*SEQ + n0 + r0 + row_a + 8]) * MASK_NEG;

    float Oacc[32];
    #pragma unroll
    for (int i = 0; i < 32; i++) Oacc[i] = 0.f;
    float mstat[2] = {-1e30f, -1e30f};
    float lstat[2] = {0.f, 0.f};

    for (int kt = 0; kt < SEQ / 64; kt++) {
        cp_async_wait0();
        __syncthreads();
        const uint32_t buf = sbase + (uint32_t)((kt & 1) * FB_SIZE);

        if (kt + 1 < SEQ / 64) {
            const uint32_t nbuf = sbase + (uint32_t)(((kt + 1) & 1) * FB_SIZE);
            const long gb = baseKV + ((long)(kt + 1) << 12);
            #pragma unroll
            for (int p = 0; p < 4; p++) {
                int idx = tid + p * 128;
                int r = idx >> 3, c8 = (idx & 7) << 3;
                uint32_t doff = (uint32_t)((r * 72 + c8) << 1);
                long go = gb + (r << 6) + c8;
                cp_async16(nbuf + FB_KHI + doff, KH + go);
                cp_async16(nbuf + FB_KLO + doff, KL + go);
                cp_async16(nbuf + FB_VHI + doff, VH + go);
                cp_async16(nbuf + FB_VLO + doff, VL + go);
            }
            cp_async_commit();
        }

        float S1[32], S2[32];
        #pragma unroll
        for (int i = 0; i < 32; i++) { S1[i] = 0.f; S2[i] = 0.f; }

        const uint32_t khi_b = buf + FB_KHI;
        const uint32_t klo_b = buf + FB_KLO;
        #pragma unroll
        for (int s = 0; s < 4; s++) {
            #pragma unroll
            for (int jk = 0; jk < 4; jk++) {
                uint32_t off = (uint32_t)((((jk << 4) + lmn_key) * 72
                                           + (s << 4) + lmn_d) << 1);
                uint32_t h0, h1, h2, h3, l0, l1, l2, l3;
                ldmx4(h0, h1, h2, h3, khi_b + off);
                ldmx4(l0, l1, l2, l3, klo_b + off);
                int j0 = jk * 2;
                mma_fp16(&S1[j0*4], qh[s],  h0, h1);
                mma_fp16(&S2[j0*4], qls[s], h0, h1);
                mma_fp16(&S2[j0*4], qh[s],  l0, l1);
                mma_fp16(&S1[(j0+1)*4], qh[s],  h2, h3);
                mma_fp16(&S2[(j0+1)*4], qls[s], h2, h3);
                mma_fp16(&S2[(j0+1)*4], qh[s],  l2, l3);
            }
        }

        float S[32];
        #pragma unroll
        for (int i = 0; i < 32; i++)
            S[i] = fmaf(S2[i], 4.8828125e-4f, S1[i]);

        #pragma unroll
        for (int t = 0; t < 2; t++) {
            float pent = t ? pen1 : pen0;
            float mloc = -1e30f;
            #pragma unroll
            for (int j = 0; j < 8; j++) {
                float v0 = S[j*4 + 2*t]     * ATT_SCALE - pent;
                float v1 = S[j*4 + 2*t + 1] * ATT_SCALE - pent;
                S[j*4 + 2*t]     = v0;
                S[j*4 + 2*t + 1] = v1;
                mloc = fmaxf(mloc, fmaxf(v0, v1));
            }
            mloc = fmaxf(mloc, __shfl_xor_sync(0xffffffffu, mloc, 1));
            mloc = fmaxf(mloc, __shfl_xor_sync(0xffffffffu, mloc, 2));
            float mnew  = fmaxf(mstat[t], mloc);
            float alpha = __expf(mstat[t] - mnew);
            float lloc = 0.f;
            #pragma unroll
            for (int j = 0; j < 8; j++) {
                float p0 = __expf(S[j*4 + 2*t]     - mnew);
                float p1 = __expf(S[j*4 + 2*t + 1] - mnew);
                S[j*4 + 2*t]     = p0;
                S[j*4 + 2*t + 1] = p1;
                lloc += p0 + p1;
            }
            lloc += __shfl_xor_sync(0xffffffffu, lloc, 1);
            lloc += __shfl_xor_sync(0xffffffffu, lloc, 2);
            lstat[t] = lstat[t] * alpha + lloc;
            mstat[t] = mnew;
            #pragma unroll
            for (int j = 0; j < 8; j++) {
                Oacc[j*4 + 2*t]     *= alpha;
                Oacc[j*4 + 2*t + 1] *= alpha;
            }
        }

        const uint32_t vhi_b = buf + FB_VHI;
        const uint32_t vlo_b = buf + FB_VLO;
        #pragma unroll
        for (int t2 = 0; t2 < 4; t2++) {
            uint32_t ah[4], al[4];
            #pragma unroll
            for (int i = 0; i < 4; i++) {
                int jt  = 2*t2 + (i >> 1);
                int off = (i & 1) * 2;
                float p0 = S[jt*4 + off];
                float p1 = S[jt*4 + off + 1];
                uint32_t hh = pack_bf16x2(p0, p1);
                ah[i] = hh;
                al[i] = pack_bf16x2(p0 - __uint_as_float(hh << 16),
                                    p1 - __uint_as_float(hh & 0xFFFF0000u));
            }
            const uint32_t row_off =
                (uint32_t)(((t2 * 16 + lmt_k) * 72 + lmt_d) * 2);
            #pragma unroll
            for (int j2 = 0; j2 < 4; j2++) {
                uint32_t off = row_off + (uint32_t)(j2 * 16 * 2);
                uint32_t h0, h1, h2, h3, l0, l1, l2, l3;
                ldmx4t(h0, h1, h2, h3, vhi_b + off);
                ldmx4t(l0, l1, l2, l3, vlo_b + off);
                mma_bf16(&Oacc[(2*j2)*4], ah, h0, h1);
                mma_bf16(&Oacc[(2*j2)*4], al, h0, h1);
                mma_bf16(&Oacc[(2*j2)*4], ah, l0, l1);
                mma_bf16(&Oacc[(2*j2+1)*4], ah, h2, h3);
                mma_bf16(&Oacc[(2*j2+1)*4], al, h2, h3);
                mma_bf16(&Oacc[(2*j2+1)*4], ah, l2, l3);
            }
        }
    }

    // ---- normalize + store as bf16 hi/lo (out-proj A operand) ----
    float inv0 = 1.f / lstat[0];
    float inv1 = 1.f / lstat[1];
    int rowg = n0 + r0 + row_a;
    #pragma unroll
    for (int j = 0; j < 8; j++) {
        int col = (h << 6) + j * 8 + 2 * colc;
        float a0 = Oacc[j*4 + 0] * inv0, a1 = Oacc[j*4 + 1] * inv0;
        float b0 = Oacc[j*4 + 2] * inv1, b1 = Oacc[j*4 + 3] * inv1;
        long r1o = ((long)b * SEQ + rowg) * 1024 + col;
        long r2o = ((long)b * SEQ + rowg + 8) * 1024 + col;
        uint32_t h1p = pack_bf16x2(a0, a1);
        uint32_t h2p = pack_bf16x2(b0, b1);
        *(uint32_t*)(OBH + r1o) = h1p;
        *(uint32_t*)(OBH + r2o) = h2p;
        *(uint32_t*)(OBL + r1o) =
            pack_bf16x2(a0 - __uint_as_float(h1p << 16),
                        a1 - __uint_as_float(h1p & 0xFFFF0000u));
        *(uint32_t*)(OBL + r2o) =
            pack_bf16x2(b0 - __uint_as_float(h2p << 16),
                        b1 - __uint_as_float(h2p & 0xFFFF0000u));
    }
}

// ---------------------------------------------------------------------------
// Launch
// ---------------------------------------------------------------------------
extern "C" void kernel_launch(void* const* d_in, const int* in_sizes, int n_in,
                              void* d_out, int out_size)
{
    const float* x       = (const float*)d_in[0];
    const float* context = (const float*)d_in[1];
    const int*   mask    = (const int*)d_in[2];
    const float* Wq      = (const float*)d_in[3];
    const float* Wkv     = (const float*)d_in[4];
    const float* Wout    = (const float*)d_in[5];
    const float* bout    = (const float*)d_in[6];
    float* out = (float*)d_out;

    float *q, *k, *v;
    cudaGetSymbolAddress((void**)&q, g_q);
    cudaGetSymbolAddress((void**)&k, g_k);
    cudaGetSymbolAddress((void**)&v, g_v);
    __half *kh, *kl;
    __nv_bfloat16 *vh, *vl;
    cudaGetSymbolAddress((void**)&kh, g_kh);
    cudaGetSymbolAddress((void**)&kl, g_kl);
    cudaGetSymbolAddress((void**)&vh, g_vh);
    cudaGetSymbolAddress((void**)&vl, g_vl);
    float *xh, *xl, *cth, *ctl, *wqh, *wql, *wkh, *wkl;
    cudaGetSymbolAddress((void**)&xh, g_xh);
    cudaGetSymbolAddress((void**)&xl, g_xl);
    cudaGetSymbolAddress((void**)&cth, g_cth);
    cudaGetSymbolAddress((void**)&ctl, g_ctl);
    cudaGetSymbolAddress((void**)&wqh, g_wqh);
    cudaGetSymbolAddress((void**)&wql, g_wql);
    cudaGetSymbolAddress((void**)&wkh, g_wkh);
    cudaGetSymbolAddress((void**)&wkl, g_wkl);
    __nv_bfloat16 *ctbh, *ctbl, *wvbh, *wvbl, *wobh, *wobl, *obh, *obl;
    cudaGetSymbolAddress((void**)&ctbh, g_ctbh);
    cudaGetSymbolAddress((void**)&ctbl, g_ctbl);
    cudaGetSymbolAddress((void**)&wvbh, g_wvbh);
    cudaGetSymbolAddress((void**)&wvbl, g_wvbl);
    cudaGetSymbolAddress((void**)&wobh, g_wobh);
    cudaGetSymbolAddress((void**)&wobl, g_wobl);
    cudaGetSymbolAddress((void**)&obh, g_obh);
    cudaGetSymbolAddress((void**)&obl, g_obl);

    cudaFuncSetAttribute(flash_mma,
                         cudaFuncAttributeMaxDynamicSharedMemorySize, FLASH_SMEM);
    cudaFuncSetAttribute(gemm_tf32_ps,
                         cudaFuncAttributeMaxDynamicSharedMemorySize, P32_SMEM);
    cudaFuncSetAttribute(gemm_bf16_ps,
                         cudaFuncAttributeMaxDynamicSharedMemorySize, P16_SMEM);

    // ---- one-time operand splits ----
    int nact4 = ROWS * DMODEL / 4;      // 1M
    int nw4   = DMODEL * INNER / 4;     // 256K
    split_t32<<<nact4 / 256, 256>>>(x, xh, xl, nact4);
    split_t32<<<nact4 / 256, 256>>>(context, cth, ctl, nact4);
    split_b16<<<nact4 / 256, 256>>>(context, ctbh, ctbl, nact4);
    split_t32<<<nw4 / 256, 256>>>(Wq, wqh, wql, nw4);
    split_t32_slice<<<nw4 / 256, 256>>>(Wkv, wkh, wkl, 2 * INNER, 0);
    split_b16_slice<<<nw4 / 256, 256>>>(Wkv, wvbh, wvbl, 2 * INNER, INNER);
    split_b16<<<nw4 / 256, 256>>>(Wout, wobh, wobl, nw4);

    // ---- projections ----
    dim3 gg(1024 / 128, 4096 / 128);
    gemm_tf32_ps<<<gg, 256, P32_SMEM>>>(xh, xl, wqh, wql, q);
    gemm_tf32_ps<<<gg, 256, P32_SMEM>>>(cth, ctl, wkh, wkl, k);
    gemm_bf16_ps<<<gg, 256, P16_SMEM>>>(ctbh, ctbl, wvbh, wvbl, v, nullptr);

    // ---- K/V per-head conversion ----
    convert_kv<<<nact4 / 256, 256>>>(k, v, kh, kl, vh, vl);

    // ---- attention ----
    dim3 grid_attn(SEQ / 64, HEADS, BATCH);
    flash_mma<<<grid_attn, 128, FLASH_SMEM>>>(q, kh, kl, vh, vl, mask, obh, obl);

    // ---- output projection ----
    gemm_bf16_ps<<<gg, 256, P16_SMEM>>>(obh, obl, wobh, wobl, out, bout);
}

// round 13
// speedup vs baseline: 3.2608x; 1.1816x over previous
#include <cuda_runtime.h>
#include <cuda_bf16.h>
#include <cuda_fp16.h>
#include <math.h>
#include <stdint.h>

// Problem constants
#define BATCH   2
#define SEQ     2048
#define DMODEL  1024
#define HEADS   16
#define DHEAD   64
#define INNER   (HEADS*DHEAD)      // 1024
#define ROWS    (BATCH*SEQ)        // 4096
#define ATT_SCALE 0.125f
#define MASK_NEG 1000000.0f
#define INV2048 4.8828125e-4f

// ---------------------------------------------------------------------------
// Scratch (allocation-free rule: static __device__ globals)
// ---------------------------------------------------------------------------
__device__ float g_q[ROWS*INNER];
// flash K/V operands, per-head layout [b][h][key][64]
__device__ __half        g_kh[ROWS*INNER];
__device__ __half        g_kl[ROWS*INNER];   // (k - hi) * 2048
__device__ __nv_bfloat16 g_vh[ROWS*INNER];
__device__ __nv_bfloat16 g_vl[ROWS*INNER];
// pre-split GEMM operands (fp16: lo scaled by 2048)
__device__ __half g_xfh[ROWS*DMODEL],  g_xfl[ROWS*DMODEL];
__device__ __half g_ctfh[ROWS*DMODEL], g_ctfl[ROWS*DMODEL];
__device__ __half g_wqfh[DMODEL*INNER], g_wqfl[DMODEL*INNER];
__device__ __half g_wkfh[DMODEL*INNER], g_wkfl[DMODEL*INNER];
__device__ __nv_bfloat16 g_ctbh[ROWS*DMODEL], g_ctbl[ROWS*DMODEL];
__device__ __nv_bfloat16 g_wvbh[DMODEL*INNER], g_wvbl[DMODEL*INNER];
__device__ __nv_bfloat16 g_wobh[INNER*DMODEL], g_wobl[INNER*DMODEL];
__device__ __nv_bfloat16 g_obh[ROWS*INNER], g_obl[ROWS*INNER];

// ---------------------------------------------------------------------------
// mma.sync / ldmatrix / cp.async helpers (compute_103-compatible; NO tcgen05)
// ---------------------------------------------------------------------------
__device__ __forceinline__ void mma_bf16(float* d, const uint32_t* a,
                                         uint32_t b0, uint32_t b1)
{
    asm volatile(
        "mma.sync.aligned.m16n8k16.row.col.f32.bf16.bf16.f32 "
        "{%0,%1,%2,%3}, {%4,%5,%6,%7}, {%8,%9}, {%0,%1,%2,%3};"
        : "+f"(d[0]), "+f"(d[1]), "+f"(d[2]), "+f"(d[3])
        : "r"(a[0]), "r"(a[1]), "r"(a[2]), "r"(a[3]), "r"(b0), "r"(b1));
}

__device__ __forceinline__ void mma_fp16(float* d, const uint32_t* a,
                                         uint32_t b0, uint32_t b1)
{
    asm volatile(
        "mma.sync.aligned.m16n8k16.row.col.f32.f16.f16.f32 "
        "{%0,%1,%2,%3}, {%4,%5,%6,%7}, {%8,%9}, {%0,%1,%2,%3};"
        : "+f"(d[0]), "+f"(d[1]), "+f"(d[2]), "+f"(d[3])
        : "r"(a[0]), "r"(a[1]), "r"(a[2]), "r"(a[3]), "r"(b0), "r"(b1));
}

__device__ __forceinline__ uint32_t pack_bf16x2(float lo_val, float hi_val) {
    uint32_t r;
    asm("cvt.rn.bf16x2.f32 %0, %1, %2;" : "=r"(r) : "f"(hi_val), "f"(lo_val));
    return r;
}

__device__ __forceinline__ uint32_t pack_f16x2(float lo_val, float hi_val) {
    __half h0 = __float2half_rn(lo_val);
    __half h1 = __float2half_rn(hi_val);
    return ((uint32_t)__half_as_ushort(h1) << 16) | __half_as_ushort(h0);
}

__device__ __forceinline__ void ldmx4t(uint32_t& r0, uint32_t& r1,
                                       uint32_t& r2, uint32_t& r3, uint32_t addr)
{
    asm volatile(
        "ldmatrix.sync.aligned.m8n8.x4.trans.shared.b16 {%0,%1,%2,%3}, [%4];"
        : "=r"(r0), "=r"(r1), "=r"(r2), "=r"(r3) : "r"(addr));
}
__device__ __forceinline__ void ldmx4(uint32_t& r0, uint32_t& r1,
                                      uint32_t& r2, uint32_t& r3, uint32_t addr)
{
    asm volatile(
        "ldmatrix.sync.aligned.m8n8.x4.shared.b16 {%0,%1,%2,%3}, [%4];"
        : "=r"(r0), "=r"(r1), "=r"(r2), "=r"(r3) : "r"(addr));
}

__device__ __forceinline__ void cp_async16(uint32_t saddr, const void* gptr) {
    asm volatile("cp.async.cg.shared.global [%0], [%1], 16;"
                 :: "r"(saddr), "l"(gptr));
}
__device__ __forceinline__ void cp_async_commit() {
    asm volatile("cp.async.commit_group;");
}
__device__ __forceinline__ void cp_async_wait0() {
    asm volatile("cp.async.wait_group 0;");
}
__device__ __forceinline__ void cp_async_wait1() {
    asm volatile("cp.async.wait_group 1;");
}

// ===========================================================================
// One-time operand split kernels
// ===========================================================================
__global__ void split_f16(const float* __restrict__ src,
                          __half* __restrict__ hi, __half* __restrict__ lo,
                          int n4)
{
    int i = blockIdx.x * blockDim.x + threadIdx.x;
    if (i >= n4) return;
    float4 x = ((const float4*)src)[i];
    float a[4] = {x.x, x.y, x.z, x.w};
    uint32_t hp[2], lp[2];
    #pragma unroll
    for (int p = 0; p < 2; p++) {
        __half h0 = __float2half_rn(a[2*p]);
        __half h1 = __float2half_rn(a[2*p+1]);
        hp[p] = ((uint32_t)__half_as_ushort(h1) << 16) | __half_as_ushort(h0);
        lp[p] = pack_f16x2((a[2*p]   - __half2float(h0)) * 2048.f,
                           (a[2*p+1] - __half2float(h1)) * 2048.f);
    }
    ((uint2*)hi)[i] = make_uint2(hp[0], hp[1]);
    ((uint2*)lo)[i] = make_uint2(lp[0], lp[1]);
}

__global__ void split_f16_slice(const float* __restrict__ src,
                                __half* __restrict__ hi, __half* __restrict__ lo,
                                int cols_src, int col0)
{
    int i = blockIdx.x * blockDim.x + threadIdx.x;
    if (i >= DMODEL * INNER / 4) return;
    int e = i * 4;
    int r = e >> 10, c = e & 1023;
    float4 x = *(const float4*)(src + (long)r * cols_src + col0 + c);
    float a[4] = {x.x, x.y, x.z, x.w};
    uint32_t hp[2], lp[2];
    #pragma unroll
    for (int p = 0; p < 2; p++) {
        __half h0 = __float2half_rn(a[2*p]);
        __half h1 = __float2half_rn(a[2*p+1]);
        hp[p] = ((uint32_t)__half_as_ushort(h1) << 16) | __half_as_ushort(h0);
        lp[p] = pack_f16x2((a[2*p]   - __half2float(h0)) * 2048.f,
                           (a[2*p+1] - __half2float(h1)) * 2048.f);
    }
    ((uint2*)hi)[i] = make_uint2(hp[0], hp[1]);
    ((uint2*)lo)[i] = make_uint2(lp[0], lp[1]);
}

__global__ void split_b16(const float* __restrict__ src,
                          __nv_bfloat16* __restrict__ hi,
                          __nv_bfloat16* __restrict__ lo, int n4)
{
    int i = blockIdx.x * blockDim.x + threadIdx.x;
    if (i >= n4) return;
    float4 x = ((const float4*)src)[i];
    uint2 h, l;
    h.x = pack_bf16x2(x.x, x.y);
    h.y = pack_bf16x2(x.z, x.w);
    l.x = pack_bf16x2(x.x - __uint_as_float(h.x << 16),
                      x.y - __uint_as_float(h.x & 0xFFFF0000u));
    l.y = pack_bf16x2(x.z - __uint_as_float(h.y << 16),
                      x.w - __uint_as_float(h.y & 0xFFFF0000u));
    ((uint2*)hi)[i] = h;
    ((uint2*)lo)[i] = l;
}

__global__ void split_b16_slice(const float* __restrict__ src,
                                __nv_bfloat16* __restrict__ hi,
                                __nv_bfloat16* __restrict__ lo,
                                int cols_src, int col0)
{
    int i = blockIdx.x * blockDim.x + threadIdx.x;
    if (i >= DMODEL * INNER / 4) return;
    int e = i * 4;
    int r = e >> 10, c = e & 1023;
    float4 x = *(const float4*)(src + (long)r * cols_src + col0 + c);
    uint2 h, l;
    h.x = pack_bf16x2(x.x, x.y);
    h.y = pack_bf16x2(x.z, x.w);
    l.x = pack_bf16x2(x.x - __uint_as_float(h.x << 16),
                      x.y - __uint_as_float(h.x & 0xFFFF0000u));
    l.y = pack_bf16x2(x.z - __uint_as_float(h.y << 16),
                      x.w - __uint_as_float(h.y & 0xFFFF0000u));
    ((uint2*)hi)[i] = h;
    ((uint2*)lo)[i] = l;
}

// ===========================================================================
// Shared 16-bit GEMM skeleton: tile 128x128, chunk 32, 256 thr, 2-deep
// cp.async pipeline. Operand layouts: A [128][40] halves, B [32][136] halves.
// Epilogue modes:
//   0: C fp32 (+bias)
//   1: fp16 hi / lo*2048, per-head [b][h][key][64]    (k -> flash)
//   2: bf16 hi / lo,      per-head [b][h][key][64]    (v -> flash)
// ===========================================================================
#define P16_AHI  0
#define P16_ALO  10240          // 128*40*2
#define P16_BHI  20480
#define P16_BLO  29184          // + 32*136*2
#define P16_STAGE 37888
#define P16_SMEM (2*P16_STAGE)  // 75776

// ---- fp16 3-term (dual accumulator: S = acc1 + acc2/2048) ----
__global__ __launch_bounds__(256, 1)
void gemm_fp16_ps(const __half* __restrict__ Ah, const __half* __restrict__ Al,
                  const __half* __restrict__ Bh, const __half* __restrict__ Bl,
                  float* __restrict__ C, int mode,
                  __half* __restrict__ PH, __half* __restrict__ PL)
{
    extern __shared__ char smem[];
    const uint32_t sbase = (uint32_t)__cvta_generic_to_shared(smem);

    const int tid = threadIdx.x;
    const int wid = tid >> 5;
    const int lane = tid & 31;
    const int row_a = lane >> 2;
    const int colc  = lane & 3;
    const int lm_k = lane & 15;
    const int lm_d = (lane >> 4) * 8;
    const int m0  = (wid >> 1) * 32;
    const int n0w = (wid & 1) * 64;
    const int rowBase = blockIdx.y * 128;
    const int colBase = blockIdx.x * 128;

    auto load_stage = [&](int stg, int kc) {
        const uint32_t sb = sbase + (uint32_t)(stg * P16_STAGE);
        const long ka = (long)kc * 32;
        #pragma unroll
        for (int p = 0; p < 2; p++) {
            int idx = tid + p * 256;
            int r = idx >> 2, c = (idx & 3) << 3;
            long ga = (long)(rowBase + r) * 1024 + ka + c;
            uint32_t da = (uint32_t)(r * 80 + c * 2);
            cp_async16(sb + P16_AHI + da, Ah + ga);
            cp_async16(sb + P16_ALO + da, Al + ga);
            int rb = idx >> 4, cb = (idx & 15) << 3;
            long gb = (ka + rb) * 1024 + colBase + cb;
            uint32_t db = (uint32_t)(rb * 272 + cb * 2);
            cp_async16(sb + P16_BHI + db, Bh + gb);
            cp_async16(sb + P16_BLO + db, Bl + gb);
        }
    };

    load_stage(0, 0);
    cp_async_commit();

    float ac1[2][8][4], ac2[2][8][4];
    #pragma unroll
    for (int m = 0; m < 2; m++)
        #pragma unroll
        for (int j = 0; j < 8; j++)
            #pragma unroll
            for (int c = 0; c < 4; c++) { ac1[m][j][c] = 0.f; ac2[m][j][c] = 0.f; }

    for (int kc = 0; kc < 32; kc++) {
        if (kc + 1 < 32) {
            load_stage((kc + 1) & 1, kc + 1);
            cp_async_commit();
            cp_async_wait1();
        } else {
            cp_async_wait0();
        }
        __syncthreads();

        const char* buf = smem + (kc & 1) * P16_STAGE;
        const __half* Ahi = (const __half*)(buf + P16_AHI);
        const __half* Alo = (const __half*)(buf + P16_ALO);
        const uint32_t bhi_base = sbase + (uint32_t)((kc & 1) * P16_STAGE) + P16_BHI;
        const uint32_t blo_base = sbase + (uint32_t)((kc & 1) * P16_STAGE) + P16_BLO;

        #pragma unroll
        for (int s = 0; s < 2; s++) {
            const int kb = s * 16;
            uint32_t ah0[4], as0[4], ah1[4], as1[4];
            #pragma unroll
            for (int i = 0; i < 4; i++) {
                int rr = m0 + row_a + ((i & 1) << 3);
                int kk = kb + 2 * colc + ((i >> 1) << 3);
                ah0[i] = *(const uint32_t*)&Ahi[rr * 40 + kk];
                as0[i] = *(const uint32_t*)&Alo[rr * 40 + kk];
                ah1[i] = *(const uint32_t*)&Ahi[(rr + 16) * 40 + kk];
                as1[i] = *(const uint32_t*)&Alo[(rr + 16) * 40 + kk];
            }
            #pragma unroll
            for (int j2 = 0; j2 < 4; j2++) {
                uint32_t off =
                    (uint32_t)(((kb + lm_k) * 136 + n0w + j2 * 16 + lm_d) * 2);
                uint32_t h0, h1, h2, h3, l0, l1, l2, l3;
                ldmx4t(h0, h1, h2, h3, bhi_base + off);
                ldmx4t(l0, l1, l2, l3, blo_base + off);
                int jn = j2 * 2;
                mma_fp16(ac1[0][jn], ah0, h0, h1);
                mma_fp16(ac2[0][jn], as0, h0, h1);
                mma_fp16(ac2[0][jn], ah0, l0, l1);
                mma_fp16(ac1[1][jn], ah1, h0, h1);
                mma_fp16(ac2[1][jn], as1, h0, h1);
                mma_fp16(ac2[1][jn], ah1, l0, l1);
                mma_fp16(ac1[0][jn+1], ah0, h2, h3);
                mma_fp16(ac2[0][jn+1], as0, h2, h3);
                mma_fp16(ac2[0][jn+1], ah0, l2, l3);
                mma_fp16(ac1[1][jn+1], ah1, h2, h3);
                mma_fp16(ac2[1][jn+1], as1, h2, h3);
                mma_fp16(ac2[1][jn+1], ah1, l2, l3);
            }
        }
        __syncthreads();
    }

    #pragma unroll
    for (int j = 0; j < 8; j++) {
        int col = colBase + n0w + j * 8 + 2 * colc;
        #pragma unroll
        for (int m = 0; m < 2; m++) {
            int row0 = rowBase + m0 + m * 16 + row_a;
            float v00 = fmaf(ac2[m][j][0], INV2048, ac1[m][j][0]);
            float v01 = fmaf(ac2[m][j][1], INV2048, ac1[m][j][1]);
            float v10 = fmaf(ac2[m][j][2], INV2048, ac1[m][j][2]);
            float v11 = fmaf(ac2[m][j][3], INV2048, ac1[m][j][3]);
            if (mode == 0) {
                *(float2*)(C + (long)row0 * 1024 + col) = make_float2(v00, v01);
                *(float2*)(C + (long)(row0 + 8) * 1024 + col) = make_float2(v10, v11);
            } else {
                // fp16 hi / lo*2048, per-head layout
                int h = col >> 6, d = col & 63;
                #pragma unroll
                for (int rr = 0; rr < 2; rr++) {
                    int row = row0 + rr * 8;
                    float va = rr ? v10 : v00;
                    float vb = rr ? v11 : v01;
                    int bb = row >> 11, key = row & 2047;
                    long o = (((long)(bb * HEADS + h) * SEQ + key) << 6) + d;
                    __half h0 = __float2half_rn(va);
                    __half h1 = __float2half_rn(vb);
                    *(uint32_t*)(PH + o) =
                        ((uint32_t)__half_as_ushort(h1) << 16) | __half_as_ushort(h0);
                    *(uint32_t*)(PL + o) =
                        pack_f16x2((va - __half2float(h0)) * 2048.f,
                                   (vb - __half2float(h1)) * 2048.f);
                }
            }
        }
    }
}

// ---- bf16 3-term ----
__global__ __launch_bounds__(256, 1)
void gemm_bf16_ps(const __nv_bfloat16* __restrict__ Ah,
                  const __nv_bfloat16* __restrict__ Al,
                  const __nv_bfloat16* __restrict__ Bh,
                  const __nv_bfloat16* __restrict__ Bl,
                  float* __restrict__ C, const float* __restrict__ bias,
                  int mode,
                  __nv_bfloat16* __restrict__ PH, __nv_bfloat16* __restrict__ PL)
{
    extern __shared__ char smem[];
    const uint32_t sbase = (uint32_t)__cvta_generic_to_shared(smem);

    const int tid = threadIdx.x;
    const int wid = tid >> 5;
    const int lane = tid & 31;
    const int row_a = lane >> 2;
    const int colc  = lane & 3;
    const int lm_k = lane & 15;
    const int lm_d = (lane >> 4) * 8;
    const int m0  = (wid >> 1) * 32;
    const int n0w = (wid & 1) * 64;
    const int rowBase = blockIdx.y * 128;
    const int colBase = blockIdx.x * 128;

    auto load_stage = [&](int stg, int kc) {
        const uint32_t sb = sbase + (uint32_t)(stg * P16_STAGE);
        const long ka = (long)kc * 32;
        #pragma unroll
        for (int p = 0; p < 2; p++) {
            int idx = tid + p * 256;
            int r = idx >> 2, c = (idx & 3) << 3;
            long ga = (long)(rowBase + r) * 1024 + ka + c;
            uint32_t da = (uint32_t)(r * 80 + c * 2);
            cp_async16(sb + P16_AHI + da, Ah + ga);
            cp_async16(sb + P16_ALO + da, Al + ga);
            int rb = idx >> 4, cb = (idx & 15) << 3;
            long gb = (ka + rb) * 1024 + colBase + cb;
            uint32_t db = (uint32_t)(rb * 272 + cb * 2);
            cp_async16(sb + P16_BHI + db, Bh + gb);
            cp_async16(sb + P16_BLO + db, Bl + gb);
        }
    };

    load_stage(0, 0);
    cp_async_commit();

    float acc[2][8][4];
    #pragma unroll
    for (int m = 0; m < 2; m++)
        #pragma unroll
        for (int j = 0; j < 8; j++)
            #pragma unroll
            for (int c = 0; c < 4; c++) acc[m][j][c] = 0.f;

    for (int kc = 0; kc < 32; kc++) {
        if (kc + 1 < 32) {
            load_stage((kc + 1) & 1, kc + 1);
            cp_async_commit();
            cp_async_wait1();
        } else {
            cp_async_wait0();
        }
        __syncthreads();

        const char* buf = smem + (kc & 1) * P16_STAGE;
        const __nv_bfloat16* Ahi = (const __nv_bfloat16*)(buf + P16_AHI);
        const __nv_bfloat16* Alo = (const __nv_bfloat16*)(buf + P16_ALO);
        const uint32_t bhi_base = sbase + (uint32_t)((kc & 1) * P16_STAGE) + P16_BHI;
        const uint32_t blo_base = sbase + (uint32_t)((kc & 1) * P16_STAGE) + P16_BLO;

        #pragma unroll
        for (int s = 0; s < 2; s++) {
            const int kb = s * 16;
            uint32_t ah0[4], al0[4], ah1[4], al1[4];
            #pragma unroll
            for (int i = 0; i < 4; i++) {
                int rr = m0 + row_a + ((i & 1) << 3);
                int kk = kb + 2 * colc + ((i >> 1) << 3);
                ah0[i] = *(const uint32_t*)&Ahi[rr * 40 + kk];
                al0[i] = *(const uint32_t*)&Alo[rr * 40 + kk];
                ah1[i] = *(const uint32_t*)&Ahi[(rr + 16) * 40 + kk];
                al1[i] = *(const uint32_t*)&Alo[(rr + 16) * 40 + kk];
            }
            #pragma unroll
            for (int j2 = 0; j2 < 4; j2++) {
                uint32_t off =
                    (uint32_t)(((kb + lm_k) * 136 + n0w + j2 * 16 + lm_d) * 2);
                uint32_t h0, h1, h2, h3, l0, l1, l2, l3;
                ldmx4t(h0, h1, h2, h3, bhi_base + off);
                ldmx4t(l0, l1, l2, l3, blo_base + off);
                int jn = j2 * 2;
                mma_bf16(acc[0][jn], ah0, h0, h1);
                mma_bf16(acc[0][jn], al0, h0, h1);
                mma_bf16(acc[0][jn], ah0, l0, l1);
                mma_bf16(acc[1][jn], ah1, h0, h1);
                mma_bf16(acc[1][jn], al1, h0, h1);
                mma_bf16(acc[1][jn], ah1, l0, l1);
                mma_bf16(acc[0][jn+1], ah0, h2, h3);
                mma_bf16(acc[0][jn+1], al0, h2, h3);
                mma_bf16(acc[0][jn+1], ah0, l2, l3);
                mma_bf16(acc[1][jn+1], ah1, h2, h3);
                mma_bf16(acc[1][jn+1], al1, h2, h3);
                mma_bf16(acc[1][jn+1], ah1, l2, l3);
            }
        }
        __syncthreads();
    }

    #pragma unroll
    for (int j = 0; j < 8; j++) {
        int col = colBase + n0w + j * 8 + 2 * colc;
        float bx = (mode == 0 && bias) ? bias[col] : 0.f;
        float by = (mode == 0 && bias) ? bias[col + 1] : 0.f;
        #pragma unroll
        for (int m = 0; m < 2; m++) {
            int row0 = rowBase + m0 + m * 16 + row_a;
            if (mode == 0) {
                *(float2*)(C + (long)row0 * 1024 + col) =
                    make_float2(acc[m][j][0] + bx, acc[m][j][1] + by);
                *(float2*)(C + (long)(row0 + 8) * 1024 + col) =
                    make_float2(acc[m][j][2] + bx, acc[m][j][3] + by);
            } else {
                int h = col >> 6, d = col & 63;
                #pragma unroll
                for (int rr = 0; rr < 2; rr++) {
                    int row = row0 + rr * 8;
                    float va = acc[m][j][rr * 2 + 0];
                    float vb = acc[m][j][rr * 2 + 1];
                    int bb = row >> 11, key = row & 2047;
                    long o = (((long)(bb * HEADS + h) * SEQ + key) << 6) + d;
                    uint32_t hp = pack_bf16x2(va, vb);
                    *(uint32_t*)(PH + o) = hp;
                    *(uint32_t*)(PL + o) =
                        pack_bf16x2(va - __uint_as_float(hp << 16),
                                    vb - __uint_as_float(hp & 0xFFFF0000u));
                }
            }
        }
    }
}

// ===========================================================================
// Flash attention v4 (unchanged from R12 — passed, bf16 hi/lo epilogue)
// ===========================================================================
#define FB_KHI  0
#define FB_KLO  9216
#define FB_VHI  18432
#define FB_VLO  27648
#define FB_SIZE 36864
#define FLASH_SMEM (2*FB_SIZE)

__global__ __launch_bounds__(128, 2)
void flash_mma(const float* __restrict__ Q,
               const __half* __restrict__ KH, const __half* __restrict__ KL,
               const __nv_bfloat16* __restrict__ VH,
               const __nv_bfloat16* __restrict__ VL,
               const int* __restrict__ mask,
               __nv_bfloat16* __restrict__ OBH,
               __nv_bfloat16* __restrict__ OBL)
{
    extern __shared__ char smem[];
    const uint32_t sbase = (uint32_t)__cvta_generic_to_shared(smem);

    const int b  = blockIdx.z;
    const int h  = blockIdx.y;
    const int n0 = blockIdx.x * 64;

    const int tid   = threadIdx.x;
    const int wid   = tid >> 5;
    const int lane  = tid & 31;
    const int r0    = wid * 16;
    const int row_a = lane >> 2;
    const int colc  = lane & 3;

    const long baseQ  = (long)b * SEQ * DMODEL + (long)h * DHEAD;
    const long baseKV = ((long)(b * HEADS + h) * SEQ) << 6;

    const int lmn_key = ((lane >> 4) << 3) + (lane & 7);
    const int lmn_d   = ((lane >> 3) & 1) << 3;
    const int lmt_k   = lane & 15;
    const int lmt_d   = (lane >> 4) * 8;

    #pragma unroll
    for (int p = 0; p < 4; p++) {
        int idx = tid + p * 128;
        int r = idx >> 3, c8 = (idx & 7) << 3;
        uint32_t doff = (uint32_t)((r * 72 + c8) << 1);
        long go = baseKV + (r << 6) + c8;
        cp_async16(sbase + FB_KHI + doff, KH + go);
        cp_async16(sbase + FB_KLO + doff, KL + go);
        cp_async16(sbase + FB_VHI + doff, VH + go);
        cp_async16(sbase + FB_VLO + doff, VL + go);
    }
    cp_async_commit();

    uint32_t qh[4][4], qls[4][4];
    #pragma unroll
    for (int s = 0; s < 4; s++) {
        #pragma unroll
        for (int i = 0; i < 4; i++) {
            int rr = n0 + r0 + row_a + ((i & 1) << 3);
            int kb = (s << 4) + 2 * colc + ((i >> 1) << 3);
            float q0 = Q[baseQ + (long)rr * DMODEL + kb];
            float q1 = Q[baseQ + (long)rr * DMODEL + kb + 1];
            __half h0 = __float2half_rn(q0);
            __half h1 = __float2half_rn(q1);
            qh[s][i] = ((uint32_t)__half_as_ushort(h1) << 16) | __half_as_ushort(h0);
            qls[s][i] = pack_f16x2((q0 - __half2float(h0)) * 2048.f,
                                   (q1 - __half2float(h1)) * 2048.f);
        }
    }

    const float pen0 = (1.0f - (float)mask[b*SEQ + n0 + r0 + row_a])     * MASK_NEG;
    const float pen1 = (1.0f - (float)mask[b*SEQ + n0 + r0 + row_a + 8]) * MASK_NEG;

    float Oacc[32];
    #pragma unroll
    for (int i = 0; i < 32; i++) Oacc[i] = 0.f;
    float mstat[2] = {-1e30f, -1e30f};
    float lstat[2] = {0.f, 0.f};

    for (int kt = 0; kt < SEQ / 64; kt++) {
        cp_async_wait0();
        __syncthreads();
        const uint32_t buf = sbase + (uint32_t)((kt & 1) * FB_SIZE);

        if (kt + 1 < SEQ / 64) {
            const uint32_t nbuf = sbase + (uint32_t)(((kt + 1) & 1) * FB_SIZE);
            const long gb = baseKV + ((long)(kt + 1) << 12);
            #pragma unroll
            for (int p = 0; p < 4; p++) {
                int idx = tid + p * 128;
                int r = idx >> 3, c8 = (idx & 7) << 3;
                uint32_t doff = (uint32_t)((r * 72 + c8) << 1);
                long go = gb + (r << 6) + c8;
                cp_async16(nbuf + FB_KHI + doff, KH + go);
                cp_async16(nbuf + FB_KLO + doff, KL + go);
                cp_async16(nbuf + FB_VHI + doff, VH + go);
                cp_async16(nbuf + FB_VLO + doff, VL + go);
            }
            cp_async_commit();
        }

        float S1[32], S2[32];
        #pragma unroll
        for (int i = 0; i < 32; i++) { S1[i] = 0.f; S2[i] = 0.f; }

        const uint32_t khi_b = buf + FB_KHI;
        const uint32_t klo_b = buf + FB_KLO;
        #pragma unroll
        for (int s = 0; s < 4; s++) {
            #pragma unroll
            for (int jk = 0; jk < 4; jk++) {
                uint32_t off = (uint32_t)((((jk << 4) + lmn_key) * 72
                                           + (s << 4) + lmn_d) << 1);
                uint32_t h0, h1, h2, h3, l0, l1, l2, l3;
                ldmx4(h0, h1, h2, h3, khi_b + off);
                ldmx4(l0, l1, l2, l3, klo_b + off);
                int j0 = jk * 2;
                mma_fp16(&S1[j0*4], qh[s],  h0, h1);
                mma_fp16(&S2[j0*4], qls[s], h0, h1);
                mma_fp16(&S2[j0*4], qh[s],  l0, l1);
                mma_fp16(&S1[(j0+1)*4], qh[s],  h2, h3);
                mma_fp16(&S2[(j0+1)*4], qls[s], h2, h3);
                mma_fp16(&S2[(j0+1)*4], qh[s],  l2, l3);
            }
        }

        float S[32];
        #pragma unroll
        for (int i = 0; i < 32; i++)
            S[i] = fmaf(S2[i], INV2048, S1[i]);

        #pragma unroll
        for (int t = 0; t < 2; t++) {
            float pent = t ? pen1 : pen0;
            float mloc = -1e30f;
            #pragma unroll
            for (int j = 0; j < 8; j++) {
                float v0 = S[j*4 + 2*t]     * ATT_SCALE - pent;
                float v1 = S[j*4 + 2*t + 1] * ATT_SCALE - pent;
                S[j*4 + 2*t]     = v0;
                S[j*4 + 2*t + 1] = v1;
                mloc = fmaxf(mloc, fmaxf(v0, v1));
            }
            mloc = fmaxf(mloc, __shfl_xor_sync(0xffffffffu, mloc, 1));
            mloc = fmaxf(mloc, __shfl_xor_sync(0xffffffffu, mloc, 2));
            float mnew  = fmaxf(mstat[t], mloc);
            float alpha = __expf(mstat[t] - mnew);
            float lloc = 0.f;
            #pragma unroll
            for (int j = 0; j < 8; j++) {
                float p0 = __expf(S[j*4 + 2*t]     - mnew);
                float p1 = __expf(S[j*4 + 2*t + 1] - mnew);
                S[j*4 + 2*t]     = p0;
                S[j*4 + 2*t + 1] = p1;
                lloc += p0 + p1;
            }
            lloc += __shfl_xor_sync(0xffffffffu, lloc, 1);
            lloc += __shfl_xor_sync(0xffffffffu, lloc, 2);
            lstat[t] = lstat[t] * alpha + lloc;
            mstat[t] = mnew;
            #pragma unroll
            for (int j = 0; j < 8; j++) {
                Oacc[j*4 + 2*t]     *= alpha;
                Oacc[j*4 + 2*t + 1] *= alpha;
            }
        }

        const uint32_t vhi_b = buf + FB_VHI;
        const uint32_t vlo_b = buf + FB_VLO;
        #pragma unroll
        for (int t2 = 0; t2 < 4; t2++) {
            uint32_t ah[4], al[4];
            #pragma unroll
            for (int i = 0; i < 4; i++) {
                int jt  = 2*t2 + (i >> 1);
                int off = (i & 1) * 2;
                float p0 = S[jt*4 + off];
                float p1 = S[jt*4 + off + 1];
                uint32_t hh = pack_bf16x2(p0, p1);
                ah[i] = hh;
                al[i] = pack_bf16x2(p0 - __uint_as_float(hh << 16),
                                    p1 - __uint_as_float(hh & 0xFFFF0000u));
            }
            const uint32_t row_off =
                (uint32_t)(((t2 * 16 + lmt_k) * 72 + lmt_d) * 2);
            #pragma unroll
            for (int j2 = 0; j2 < 4; j2++) {
                uint32_t off = row_off + (uint32_t)(j2 * 16 * 2);
                uint32_t h0, h1, h2, h3, l0, l1, l2, l3;
                ldmx4t(h0, h1, h2, h3, vhi_b + off);
                ldmx4t(l0, l1, l2, l3, vlo_b + off);
                mma_bf16(&Oacc[(2*j2)*4], ah, h0, h1);
                mma_bf16(&Oacc[(2*j2)*4], al, h0, h1);
                mma_bf16(&Oacc[(2*j2)*4], ah, l0, l1);
                mma_bf16(&Oacc[(2*j2+1)*4], ah, h2, h3);
                mma_bf16(&Oacc[(2*j2+1)*4], al, h2, h3);
                mma_bf16(&Oacc[(2*j2+1)*4], ah, l2, l3);
            }
        }
    }

    float inv0 = 1.f / lstat[0];
    float inv1 = 1.f / lstat[1];
    int rowg = n0 + r0 + row_a;
    #pragma unroll
    for (int j = 0; j < 8; j++) {
        int col = (h << 6) + j * 8 + 2 * colc;
        float a0 = Oacc[j*4 + 0] * inv0, a1 = Oacc[j*4 + 1] * inv0;
        float b0 = Oacc[j*4 + 2] * inv1, b1 = Oacc[j*4 + 3] * inv1;
        long r1o = ((long)b * SEQ + rowg) * 1024 + col;
        long r2o = ((long)b * SEQ + rowg + 8) * 1024 + col;
        uint32_t h1p = pack_bf16x2(a0, a1);
        uint32_t h2p = pack_bf16x2(b0, b1);
        *(uint32_t*)(OBH + r1o) = h1p;
        *(uint32_t*)(OBH + r2o) = h2p;
        *(uint32_t*)(OBL + r1o) =
            pack_bf16x2(a0 - __uint_as_float(h1p << 16),
                        a1 - __uint_as_float(h1p & 0xFFFF0000u));
        *(uint32_t*)(OBL + r2o) =
            pack_bf16x2(b0 - __uint_as_float(h2p << 16),
                        b1 - __uint_as_float(h2p & 0xFFFF0000u));
    }
}

// ---------------------------------------------------------------------------
// Launch
// ---------------------------------------------------------------------------
extern "C" void kernel_launch(void* const* d_in, const int* in_sizes, int n_in,
                              void* d_out, int out_size)
{
    const float* x       = (const float*)d_in[0];
    const float* context = (const float*)d_in[1];
    const int*   mask    = (const int*)d_in[2];
    const float* Wq      = (const float*)d_in[3];
    const float* Wkv     = (const float*)d_in[4];
    const float* Wout    = (const float*)d_in[5];
    const float* bout    = (const float*)d_in[6];
    float* out = (float*)d_out;

    float* q;
    cudaGetSymbolAddress((void**)&q, g_q);
    __half *kh, *kl;
    __nv_bfloat16 *vh, *vl;
    cudaGetSymbolAddress((void**)&kh, g_kh);
    cudaGetSymbolAddress((void**)&kl, g_kl);
    cudaGetSymbolAddress((void**)&vh, g_vh);
    cudaGetSymbolAddress((void**)&vl, g_vl);
    __half *xfh, *xfl, *ctfh, *ctfl, *wqfh, *wqfl, *wkfh, *wkfl;
    cudaGetSymbolAddress((void**)&xfh, g_xfh);
    cudaGetSymbolAddress((void**)&xfl, g_xfl);
    cudaGetSymbolAddress((void**)&ctfh, g_ctfh);
    cudaGetSymbolAddress((void**)&ctfl, g_ctfl);
    cudaGetSymbolAddress((void**)&wqfh, g_wqfh);
    cudaGetSymbolAddress((void**)&wqfl, g_wqfl);
    cudaGetSymbolAddress((void**)&wkfh, g_wkfh);
    cudaGetSymbolAddress((void**)&wkfl, g_wkfl);
    __nv_bfloat16 *ctbh, *ctbl, *wvbh, *wvbl, *wobh, *wobl, *obh, *obl;
    cudaGetSymbolAddress((void**)&ctbh, g_ctbh);
    cudaGetSymbolAddress((void**)&ctbl, g_ctbl);
    cudaGetSymbolAddress((void**)&wvbh, g_wvbh);
    cudaGetSymbolAddress((void**)&wvbl, g_wvbl);
    cudaGetSymbolAddress((void**)&wobh, g_wobh);
    cudaGetSymbolAddress((void**)&wobl, g_wobl);
    cudaGetSymbolAddress((void**)&obh, g_obh);
    cudaGetSymbolAddress((void**)&obl, g_obl);

    cudaFuncSetAttribute(flash_mma,
                         cudaFuncAttributeMaxDynamicSharedMemorySize, FLASH_SMEM);
    cudaFuncSetAttribute(gemm_fp16_ps,
                         cudaFuncAttributeMaxDynamicSharedMemorySize, P16_SMEM);
    cudaFuncSetAttribute(gemm_bf16_ps,
                         cudaFuncAttributeMaxDynamicSharedMemorySize, P16_SMEM);

    // ---- one-time operand splits ----
    int nact4 = ROWS * DMODEL / 4;
    int nw4   = DMODEL * INNER / 4;
    split_f16<<<nact4 / 256, 256>>>(x, xfh, xfl, nact4);
    split_f16<<<nact4 / 256, 256>>>(context, ctfh, ctfl, nact4);
    split_b16<<<nact4 / 256, 256>>>(context, ctbh, ctbl, nact4);
    split_f16<<<nw4 / 256, 256>>>(Wq, wqfh, wqfl, nw4);
    split_f16_slice<<<nw4 / 256, 256>>>(Wkv, wkfh, wkfl, 2 * INNER, 0);
    split_b16_slice<<<nw4 / 256, 256>>>(Wkv, wvbh, wvbl, 2 * INNER, INNER);
    split_b16<<<nw4 / 256, 256>>>(Wout, wobh, wobl, nw4);

    // ---- projections (fp16 3-term for q,k; bf16 3-term for v) ----
    dim3 gg(1024 / 128, 4096 / 128);
    gemm_fp16_ps<<<gg, 256, P16_SMEM>>>(xfh, xfl, wqfh, wqfl, q, 0, nullptr, nullptr);
    gemm_fp16_ps<<<gg, 256, P16_SMEM>>>(ctfh, ctfl, wkfh, wkfl, nullptr, 1, kh, kl);
    gemm_bf16_ps<<<gg, 256, P16_SMEM>>>(ctbh, ctbl, wvbh, wvbl, nullptr, nullptr, 2, vh, vl);

    // ---- attention ----
    dim3 grid_attn(SEQ / 64, HEADS, BATCH);
    flash_mma<<<grid_attn, 128, FLASH_SMEM>>>(q, kh, kl, vh, vl, mask, obh, obl);

    // ---- output projection ----
    gemm_bf16_ps<<<gg, 256, P16_SMEM>>>(obh, obl, wobh, wobl, out, bout, 0, nullptr, nullptr);
}